// round 1
// baseline (speedup 1.0000x reference)
#include <cuda_runtime.h>
#include <math.h>
#include <stdint.h>

#define NGN 12331
#define NDN 5000
#define EGG 1000000
#define EGD 400000
#define EDD 100000

// ---------------- scratch (device globals; no allocation allowed) ----------------
__device__ int g_cnt_gg_src[NGN], g_cnt_gg_dst[NGN], g_cnt_gd_src[NGN];
__device__ int g_cnt_gd_dst[NDN], g_cnt_dd_src[NDN], g_cnt_dd_dst[NDN];
__device__ int g_rp_gg[NGN + 1], g_rp_dg[NGN + 1], g_rp_gd[NDN + 1], g_rp_dd[NDN + 1];
__device__ int g_fill_gg[NGN], g_fill_dg[NGN], g_fill_gd[NDN], g_fill_dd[NDN];
__device__ int g_col_gg[EGG], g_col_dg[EGD], g_col_gd[EGD], g_col_dd[EDD];
__device__ float g_rs_gg_src[NGN], g_rs_gg_dst[NGN], g_rs_gd_src[NGN];
__device__ float g_rs_gd_dst[NDN], g_rs_dd_src[NDN], g_rs_dd_dst[NDN];
__device__ float g_hg[NGN * 64], g_hd[NDN * 64];
__device__ float g_xga[NGN * 64], g_xgb[NGN * 64];
__device__ float g_xda[NDN * 64], g_xdb[NDN * 64];
__device__ float g_og[NGN * 64], g_od[NDN * 64];

// ---------------- setup kernels ----------------
__global__ void k_zero_counts() {
    int i = blockIdx.x * blockDim.x + threadIdx.x;
    if (i < NGN) { g_cnt_gg_src[i] = 0; g_cnt_gg_dst[i] = 0; g_cnt_gd_src[i] = 0; }
    if (i < NDN) { g_cnt_gd_dst[i] = 0; g_cnt_dd_src[i] = 0; g_cnt_dd_dst[i] = 0; }
}

__global__ void k_hist(const int* __restrict__ src, const int* __restrict__ dst,
                       int* __restrict__ cs, int* __restrict__ cd, int n) {
    for (int i = blockIdx.x * blockDim.x + threadIdx.x; i < n; i += gridDim.x * blockDim.x) {
        atomicAdd(&cs[src[i]], 1);
        atomicAdd(&cd[dst[i]], 1);
    }
}

__global__ void k_rsqrt() {
    int i = blockIdx.x * blockDim.x + threadIdx.x;
    if (i < NGN) {
        g_rs_gg_src[i] = rsqrtf((float)max(g_cnt_gg_src[i], 1));
        g_rs_gg_dst[i] = rsqrtf((float)max(g_cnt_gg_dst[i], 1));
        g_rs_gd_src[i] = rsqrtf((float)max(g_cnt_gd_src[i], 1));
    }
    if (i < NDN) {
        g_rs_gd_dst[i] = rsqrtf((float)max(g_cnt_gd_dst[i], 1));
        g_rs_dd_src[i] = rsqrtf((float)max(g_cnt_dd_src[i], 1));
        g_rs_dd_dst[i] = rsqrtf((float)max(g_cnt_dd_dst[i], 1));
    }
}

// 4 independent single-block exclusive scans (one per CSR), one kernel with 4 blocks
__global__ void k_scan4() {
    const int* cnt; int* rp; int* fill; int n;
    if (blockIdx.x == 0)      { cnt = g_cnt_gg_dst; rp = g_rp_gg; fill = g_fill_gg; n = NGN; }
    else if (blockIdx.x == 1) { cnt = g_cnt_gd_src; rp = g_rp_dg; fill = g_fill_dg; n = NGN; }
    else if (blockIdx.x == 2) { cnt = g_cnt_gd_dst; rp = g_rp_gd; fill = g_fill_gd; n = NDN; }
    else                      { cnt = g_cnt_dd_dst; rp = g_rp_dd; fill = g_fill_dd; n = NDN; }
    __shared__ int ts[1024];
    const int t = threadIdx.x;
    const int C = (n + 1023) / 1024;
    int lo = t * C, hi = min((t + 1) * C, n);
    int s = 0;
    for (int i = lo; i < hi; i++) s += cnt[i];
    ts[t] = s;
    __syncthreads();
    for (int off = 1; off < 1024; off <<= 1) {
        int v = (t >= off) ? ts[t - off] : 0;
        __syncthreads();
        ts[t] += v;
        __syncthreads();
    }
    int run = ts[t] - s;  // exclusive prefix
    for (int i = lo; i < hi; i++) { rp[i] = run; fill[i] = run; run += cnt[i]; }
    if (t == 1023) rp[n] = ts[1023];
}

__global__ void k_scatter_gg(const int* __restrict__ src, const int* __restrict__ dst, int n) {
    for (int i = blockIdx.x * blockDim.x + threadIdx.x; i < n; i += gridDim.x * blockDim.x) {
        int r = dst[i];
        int p = atomicAdd(&g_fill_gg[r], 1);
        g_col_gg[p] = src[i];
    }
}
__global__ void k_scatter_gd(const int* __restrict__ src, const int* __restrict__ dst, int n) {
    for (int i = blockIdx.x * blockDim.x + threadIdx.x; i < n; i += gridDim.x * blockDim.x) {
        int s = src[i], d = dst[i];
        int p = atomicAdd(&g_fill_dg[s], 1);  // reversed relation disease->gene, rows = gd_src
        g_col_dg[p] = d;
        int q = atomicAdd(&g_fill_gd[d], 1);  // gene->disease, rows = gd_dst
        g_col_gd[q] = s;
    }
}
__global__ void k_scatter_dd(const int* __restrict__ src, const int* __restrict__ dst, int n) {
    for (int i = blockIdx.x * blockDim.x + threadIdx.x; i < n; i += gridDim.x * blockDim.x) {
        int r = dst[i];
        int p = atomicAdd(&g_fill_dd[r], 1);
        g_col_dd[p] = src[i];
    }
}

// ---------------- dense transform: X[r] = (H[r] * scale[r]) @ W.T ----------------
template <int DIN, int DOUT, int RPW>
__global__ __launch_bounds__(256) void k_transform(
    const float* __restrict__ H, const float* __restrict__ scale,
    const float* __restrict__ W, float* __restrict__ X, int nrows)
{
    constexpr int CHUNK = (DIN < 64) ? DIN : 64;
    constexpr int NCH = DIN / CHUNK;
    constexpr int OPL = DOUT / 32;  // outputs per lane
    __shared__ float Wt[CHUNK][DOUT];       // transposed chunk (k-major)
    __shared__ float hs[8][RPW][CHUNK];
    const int warp = threadIdx.x >> 5, lane = threadIdx.x & 31;
    const int rpb = 8 * RPW;
    for (int base = blockIdx.x * rpb; base < nrows; base += gridDim.x * rpb) {
        float acc[RPW][OPL];
        #pragma unroll
        for (int i = 0; i < RPW; i++)
            #pragma unroll
            for (int o = 0; o < OPL; o++) acc[i][o] = 0.f;
        for (int c = 0; c < NCH; c++) {
            __syncthreads();
            for (int i = threadIdx.x; i < CHUNK * DOUT; i += 256) {
                int k = i / DOUT, o = i - k * DOUT;
                Wt[k][o] = W[(size_t)o * DIN + c * CHUNK + k];
            }
            #pragma unroll
            for (int rr = 0; rr < RPW; rr++) {
                int r = base + warp * RPW + rr;
                if (r < nrows) {
                    float sc = scale ? scale[r] : 1.f;
                    #pragma unroll
                    for (int k = lane; k < CHUNK; k += 32)
                        hs[warp][rr][k] = H[(size_t)r * DIN + c * CHUNK + k] * sc;
                }
            }
            __syncthreads();
            #pragma unroll
            for (int k = 0; k < CHUNK; k++) {
                float w0 = Wt[k][lane];
                float w1 = (OPL > 1) ? Wt[k][(OPL > 1 ? lane + 32 : 0)] : 0.f;
                #pragma unroll
                for (int rr = 0; rr < RPW; rr++) {
                    float h = hs[warp][rr][k];
                    acc[rr][0] = fmaf(h, w0, acc[rr][0]);
                    if (OPL > 1) acc[rr][1] = fmaf(h, w1, acc[rr][1]);
                }
            }
        }
        #pragma unroll
        for (int rr = 0; rr < RPW; rr++) {
            int r = base + warp * RPW + rr;
            if (r < nrows) {
                X[(size_t)r * DOUT + lane] = acc[rr][0];
                if (OPL > 1) X[(size_t)r * DOUT + lane + 32] = acc[rr][1];
            }
        }
    }
}

// ------- fused dual-relation CSR aggregation + dst-norm + bias + relu (warp/row) -------
template <int DOUT>
__global__ __launch_bounds__(256) void k_agg(
    const int* __restrict__ rpA, const int* __restrict__ colA,
    const float* __restrict__ xA, const float* __restrict__ ndA,
    const int* __restrict__ rpB, const int* __restrict__ colB,
    const float* __restrict__ xB, const float* __restrict__ ndB,
    const float* __restrict__ bA, const float* __restrict__ bB,
    float* __restrict__ out, int nrows)
{
    const int v = blockIdx.x * (blockDim.x >> 5) + (threadIdx.x >> 5);
    const int lane = threadIdx.x & 31;
    if (v >= nrows) return;

    if (DOUT == 64) {
        float2 a = make_float2(0.f, 0.f), b = make_float2(0.f, 0.f);
        int s = rpA[v], e = rpA[v + 1], j = s;
        for (; j + 4 <= e; j += 4) {
            int u0 = colA[j], u1 = colA[j + 1], u2 = colA[j + 2], u3 = colA[j + 3];
            float2 t0 = *(const float2*)(xA + (size_t)u0 * 64 + lane * 2);
            float2 t1 = *(const float2*)(xA + (size_t)u1 * 64 + lane * 2);
            float2 t2 = *(const float2*)(xA + (size_t)u2 * 64 + lane * 2);
            float2 t3 = *(const float2*)(xA + (size_t)u3 * 64 + lane * 2);
            a.x += (t0.x + t1.x) + (t2.x + t3.x);
            a.y += (t0.y + t1.y) + (t2.y + t3.y);
        }
        for (; j < e; j++) {
            int u = colA[j];
            float2 t = *(const float2*)(xA + (size_t)u * 64 + lane * 2);
            a.x += t.x; a.y += t.y;
        }
        s = rpB[v]; e = rpB[v + 1]; j = s;
        for (; j + 4 <= e; j += 4) {
            int u0 = colB[j], u1 = colB[j + 1], u2 = colB[j + 2], u3 = colB[j + 3];
            float2 t0 = *(const float2*)(xB + (size_t)u0 * 64 + lane * 2);
            float2 t1 = *(const float2*)(xB + (size_t)u1 * 64 + lane * 2);
            float2 t2 = *(const float2*)(xB + (size_t)u2 * 64 + lane * 2);
            float2 t3 = *(const float2*)(xB + (size_t)u3 * 64 + lane * 2);
            b.x += (t0.x + t1.x) + (t2.x + t3.x);
            b.y += (t0.y + t1.y) + (t2.y + t3.y);
        }
        for (; j < e; j++) {
            int u = colB[j];
            float2 t = *(const float2*)(xB + (size_t)u * 64 + lane * 2);
            b.x += t.x; b.y += t.y;
        }
        float na = ndA[v], nb = ndB[v];
        float ox = na * a.x + nb * b.x + bA[lane * 2] + bB[lane * 2];
        float oy = na * a.y + nb * b.y + bA[lane * 2 + 1] + bB[lane * 2 + 1];
        ox = fmaxf(ox, 0.f); oy = fmaxf(oy, 0.f);
        *(float2*)(out + (size_t)v * 64 + lane * 2) = make_float2(ox, oy);
    } else {  // DOUT == 32
        float a = 0.f, b = 0.f;
        int s = rpA[v], e = rpA[v + 1], j = s;
        for (; j + 4 <= e; j += 4) {
            int u0 = colA[j], u1 = colA[j + 1], u2 = colA[j + 2], u3 = colA[j + 3];
            float t0 = xA[(size_t)u0 * 32 + lane];
            float t1 = xA[(size_t)u1 * 32 + lane];
            float t2 = xA[(size_t)u2 * 32 + lane];
            float t3 = xA[(size_t)u3 * 32 + lane];
            a += (t0 + t1) + (t2 + t3);
        }
        for (; j < e; j++) a += xA[(size_t)colA[j] * 32 + lane];
        s = rpB[v]; e = rpB[v + 1]; j = s;
        for (; j + 4 <= e; j += 4) {
            int u0 = colB[j], u1 = colB[j + 1], u2 = colB[j + 2], u3 = colB[j + 3];
            float t0 = xB[(size_t)u0 * 32 + lane];
            float t1 = xB[(size_t)u1 * 32 + lane];
            float t2 = xB[(size_t)u2 * 32 + lane];
            float t3 = xB[(size_t)u3 * 32 + lane];
            b += (t0 + t1) + (t2 + t3);
        }
        for (; j < e; j++) b += xB[(size_t)colB[j] * 32 + lane];
        float o = ndA[v] * a + ndB[v] * b + bA[lane] + bB[lane];
        out[(size_t)v * 32 + lane] = fmaxf(o, 0.f);
    }
}

// ---------------- final GEMM: C[M,N] = A[M,32] @ B[N,32]^T ----------------
__global__ __launch_bounds__(256) void k_outgemm(
    const float* __restrict__ A, const float* __restrict__ B,
    float* __restrict__ C, int M, int N)
{
    __shared__ float As[32][128];
    __shared__ float Bs[32][128];
    const int m0 = blockIdx.y * 128, n0 = blockIdx.x * 128;
    const int tid = threadIdx.x;
    for (int i = tid; i < 128 * 8; i += 256) {
        int r = i >> 3, c4 = (i & 7) << 2;
        float4 v = make_float4(0.f, 0.f, 0.f, 0.f);
        if (m0 + r < M) v = *(const float4*)(A + (size_t)(m0 + r) * 32 + c4);
        As[c4 + 0][r] = v.x; As[c4 + 1][r] = v.y; As[c4 + 2][r] = v.z; As[c4 + 3][r] = v.w;
    }
    for (int i = tid; i < 128 * 8; i += 256) {
        int r = i >> 3, c4 = (i & 7) << 2;
        float4 v = make_float4(0.f, 0.f, 0.f, 0.f);
        if (n0 + r < N) v = *(const float4*)(B + (size_t)(n0 + r) * 32 + c4);
        Bs[c4 + 0][r] = v.x; Bs[c4 + 1][r] = v.y; Bs[c4 + 2][r] = v.z; Bs[c4 + 3][r] = v.w;
    }
    __syncthreads();
    const int tx = tid & 15, ty = tid >> 4;
    float acc[8][8];
    #pragma unroll
    for (int i = 0; i < 8; i++)
        #pragma unroll
        for (int j = 0; j < 8; j++) acc[i][j] = 0.f;
    #pragma unroll
    for (int k = 0; k < 32; k++) {
        float ar[8], br[8];
        *(float4*)(ar)     = *(const float4*)&As[k][ty * 8];
        *(float4*)(ar + 4) = *(const float4*)&As[k][ty * 8 + 4];
        *(float4*)(br)     = *(const float4*)&Bs[k][tx * 8];
        *(float4*)(br + 4) = *(const float4*)&Bs[k][tx * 8 + 4];
        #pragma unroll
        for (int i = 0; i < 8; i++)
            #pragma unroll
            for (int j = 0; j < 8; j++)
                acc[i][j] = fmaf(ar[i], br[j], acc[i][j]);
    }
    #pragma unroll
    for (int i = 0; i < 8; i++) {
        int m = m0 + ty * 8 + i;
        if (m >= M) continue;
        float* cp = C + (size_t)m * N + n0 + tx * 8;
        if (n0 + tx * 8 + 8 <= N) {
            *(float4*)cp       = make_float4(acc[i][0], acc[i][1], acc[i][2], acc[i][3]);
            *(float4*)(cp + 4) = make_float4(acc[i][4], acc[i][5], acc[i][6], acc[i][7]);
        } else {
            for (int j = 0; j < 8; j++)
                if (n0 + tx * 8 + j < N) cp[j] = acc[i][j];
        }
    }
}

// ---------------- launch ----------------
#define SYMF(var, sym) do { void* _p; cudaGetSymbolAddress(&_p, sym); var = (float*)_p; } while (0)
#define SYMI(var, sym) do { void* _p; cudaGetSymbolAddress(&_p, sym); var = (int*)_p; } while (0)

extern "C" void kernel_launch(void* const* d_in, const int* in_sizes, int n_in,
                              void* d_out, int out_size)
{
    const float* feat_g = (const float*)d_in[0];
    const float* feat_d = (const float*)d_in[1];
    const int* gg_src = (const int*)d_in[2];
    const int* gg_dst = (const int*)d_in[3];
    const int* gd_src = (const int*)d_in[4];
    const int* gd_dst = (const int*)d_in[5];
    const int* dd_src = (const int*)d_in[6];
    const int* dd_dst = (const int*)d_in[7];
    const float* Wg   = (const float*)d_in[8];
    const float* Wd   = (const float*)d_in[9];
    const float* W1   = (const float*)d_in[10];
    const float* b1   = (const float*)d_in[11];
    const float* W2   = (const float*)d_in[12];
    const float* b2   = (const float*)d_in[13];
    const float* Wout = (const float*)d_in[14];
    const int n_gg = in_sizes[2], n_gd = in_sizes[4], n_dd = in_sizes[6];

    int *cnt_gg_src, *cnt_gg_dst, *cnt_gd_src;  (void)cnt_gg_src; (void)cnt_gg_dst; (void)cnt_gd_src;
    int *rp_gg, *rp_dg, *rp_gd, *rp_dd;
    int *col_gg, *col_dg, *col_gd, *col_dd;
    float *rs_gg_src, *rs_gg_dst, *rs_gd_src, *rs_gd_dst, *rs_dd_src, *rs_dd_dst;
    float *hg, *hd, *xga, *xgb, *xda, *xdb, *og, *od;
    SYMI(cnt_gg_src, g_cnt_gg_src); SYMI(cnt_gg_dst, g_cnt_gg_dst); SYMI(cnt_gd_src, g_cnt_gd_src);
    SYMI(rp_gg, g_rp_gg); SYMI(rp_dg, g_rp_dg); SYMI(rp_gd, g_rp_gd); SYMI(rp_dd, g_rp_dd);
    SYMI(col_gg, g_col_gg); SYMI(col_dg, g_col_dg); SYMI(col_gd, g_col_gd); SYMI(col_dd, g_col_dd);
    SYMF(rs_gg_src, g_rs_gg_src); SYMF(rs_gg_dst, g_rs_gg_dst); SYMF(rs_gd_src, g_rs_gd_src);
    SYMF(rs_gd_dst, g_rs_gd_dst); SYMF(rs_dd_src, g_rs_dd_src); SYMF(rs_dd_dst, g_rs_dd_dst);
    SYMF(hg, g_hg); SYMF(hd, g_hd);
    SYMF(xga, g_xga); SYMF(xgb, g_xgb); SYMF(xda, g_xda); SYMF(xdb, g_xdb);
    SYMF(og, g_og); SYMF(od, g_od);

    int *cs_gg, *cd_gg, *cs_gd, *cd_gd, *cs_dd, *cd_dd;
    SYMI(cs_gg, g_cnt_gg_src); SYMI(cd_gg, g_cnt_gg_dst);
    SYMI(cs_gd, g_cnt_gd_src); SYMI(cd_gd, g_cnt_gd_dst);
    SYMI(cs_dd, g_cnt_dd_src); SYMI(cd_dd, g_cnt_dd_dst);

    // 1) degrees + CSR build
    k_zero_counts<<<(NGN + 255) / 256, 256>>>();
    k_hist<<<1024, 256>>>(gg_src, gg_dst, cs_gg, cd_gg, n_gg);
    k_hist<<<512, 256>>>(gd_src, gd_dst, cs_gd, cd_gd, n_gd);
    k_hist<<<256, 256>>>(dd_src, dd_dst, cs_dd, cd_dd, n_dd);
    k_rsqrt<<<(NGN + 255) / 256, 256>>>();
    k_scan4<<<4, 1024>>>();
    k_scatter_gg<<<1024, 256>>>(gg_src, gg_dst, n_gg);
    k_scatter_gd<<<512, 256>>>(gd_src, gd_dst, n_gd);
    k_scatter_dd<<<256, 256>>>(dd_src, dd_dst, n_dd);

    // 2) embeddings: hg = feat_gene @ Wg.T ; hd = feat_dis @ Wd.T
    k_transform<512, 64, 4><<<(NGN + 31) / 32, 256>>>(feat_g, nullptr, Wg, hg, NGN);
    k_transform<512, 64, 4><<<(NDN + 31) / 32, 256>>>(feat_d, nullptr, Wd, hd, NDN);

    // 3) layer 1 (H1=64): pre-scale + pre-transform, then fused aggregate
    k_transform<64, 64, 2><<<(NGN + 15) / 16, 256>>>(hg, rs_gg_src, W1 + 0 * 64 * 64, xga, NGN);
    k_transform<64, 64, 2><<<(NDN + 15) / 16, 256>>>(hd, rs_gd_dst, W1 + 2 * 64 * 64, xda, NDN);
    k_transform<64, 64, 2><<<(NGN + 15) / 16, 256>>>(hg, rs_gd_src, W1 + 1 * 64 * 64, xgb, NGN);
    k_transform<64, 64, 2><<<(NDN + 15) / 16, 256>>>(hd, rs_dd_src, W1 + 3 * 64 * 64, xdb, NDN);
    k_agg<64><<<(NGN + 7) / 8, 256>>>(rp_gg, col_gg, xga, rs_gg_dst,
                                      rp_dg, col_dg, xda, rs_gd_src,
                                      b1 + 0 * 64, b1 + 2 * 64, og, NGN);
    k_agg<64><<<(NDN + 7) / 8, 256>>>(rp_gd, col_gd, xgb, rs_gd_dst,
                                      rp_dd, col_dd, xdb, rs_dd_dst,
                                      b1 + 1 * 64, b1 + 3 * 64, od, NDN);

    // 4) layer 2 (H2=32): transform first so aggregation runs at 32-dim
    k_transform<64, 32, 2><<<(NGN + 15) / 16, 256>>>(og, rs_gg_src, W2 + 0 * 32 * 64, xga, NGN);
    k_transform<64, 32, 2><<<(NDN + 15) / 16, 256>>>(od, rs_gd_dst, W2 + 2 * 32 * 64, xda, NDN);
    k_transform<64, 32, 2><<<(NGN + 15) / 16, 256>>>(og, rs_gd_src, W2 + 1 * 32 * 64, xgb, NGN);
    k_transform<64, 32, 2><<<(NDN + 15) / 16, 256>>>(od, rs_dd_src, W2 + 3 * 32 * 64, xdb, NDN);
    k_agg<32><<<(NGN + 7) / 8, 256>>>(rp_gg, col_gg, xga, rs_gg_dst,
                                      rp_dg, col_dg, xda, rs_gd_src,
                                      b2 + 0 * 32, b2 + 2 * 32, hg, NGN);   // hg2 [NG,32]
    k_agg<32><<<(NDN + 7) / 8, 256>>>(rp_gd, col_gd, xgb, rs_gd_dst,
                                      rp_dd, col_dd, xdb, rs_dd_dst,
                                      b2 + 1 * 32, b2 + 3 * 32, hd, NDN);   // hd2 [ND,32]

    // 5) A = hg2 @ Wout.T ; out = A @ hd2^T
    k_transform<32, 32, 2><<<(NGN + 15) / 16, 256>>>(hg, nullptr, Wout, xga, NGN);
    dim3 grid((NDN + 127) / 128, (NGN + 127) / 128);
    k_outgemm<<<grid, 256>>>(xga, hd, (float*)d_out, NGN, NDN);
}

// round 4
// speedup vs baseline: 1.0608x; 1.0608x over previous
#include <cuda_runtime.h>
#include <cuda_fp16.h>
#include <math.h>
#include <stdint.h>

#define NGN 12331
#define NDN 5000
#define EGG 1000000
#define EGD 400000
#define EDD 100000

// ---------------- scratch (device globals; no allocation allowed) ----------------
__device__ int g_cnt_gg_src[NGN], g_cnt_gg_dst[NGN], g_cnt_gd_src[NGN];
__device__ int g_cnt_gd_dst[NDN], g_cnt_dd_src[NDN], g_cnt_dd_dst[NDN];
__device__ int g_rp_gg[NGN + 1], g_rp_dg[NGN + 1], g_rp_gd[NDN + 1], g_rp_dd[NDN + 1];
__device__ int g_fill_gg[NGN], g_fill_dg[NGN], g_fill_gd[NDN], g_fill_dd[NDN];
__device__ int g_col_gg[EGG], g_col_dg[EGD], g_col_gd[EGD], g_col_dd[EDD];
__device__ float g_rs_gg_src[NGN], g_rs_gg_dst[NGN], g_rs_gd_src[NGN];
__device__ float g_rs_gd_dst[NDN], g_rs_dd_src[NDN], g_rs_dd_dst[NDN];
__device__ float g_hg[NGN * 64], g_hd[NDN * 64];
__device__ __align__(256) __half g_xga[NGN * 64], g_xgb[NGN * 64];
__device__ __align__(256) __half g_xda[NDN * 64], g_xdb[NDN * 64];
__device__ float g_og[NGN * 64], g_od[NDN * 64];
__device__ float g_yd[NDN * 32];

// ---------------- setup kernels ----------------
__global__ void k_zero_counts() {
    int i = blockIdx.x * blockDim.x + threadIdx.x;
    if (i < NGN) { g_cnt_gg_src[i] = 0; g_cnt_gg_dst[i] = 0; g_cnt_gd_src[i] = 0; }
    if (i < NDN) { g_cnt_gd_dst[i] = 0; g_cnt_dd_src[i] = 0; g_cnt_dd_dst[i] = 0; }
}

// one fused histogram over all 3 relations (grid-stride over concatenated ranges)
__global__ void k_hist_all(const int* __restrict__ gg_s, const int* __restrict__ gg_d,
                           const int* __restrict__ gd_s, const int* __restrict__ gd_d,
                           const int* __restrict__ dd_s, const int* __restrict__ dd_d,
                           int ngg, int ngd, int ndd) {
    const int total = ngg + ngd + ndd;
    for (int i = blockIdx.x * blockDim.x + threadIdx.x; i < total; i += gridDim.x * blockDim.x) {
        if (i < ngg) {
            atomicAdd(&g_cnt_gg_src[gg_s[i]], 1);
            atomicAdd(&g_cnt_gg_dst[gg_d[i]], 1);
        } else if (i < ngg + ngd) {
            int j = i - ngg;
            atomicAdd(&g_cnt_gd_src[gd_s[j]], 1);
            atomicAdd(&g_cnt_gd_dst[gd_d[j]], 1);
        } else {
            int j = i - ngg - ngd;
            atomicAdd(&g_cnt_dd_src[dd_s[j]], 1);
            atomicAdd(&g_cnt_dd_dst[dd_d[j]], 1);
        }
    }
}

__global__ void k_rsqrt() {
    int i = blockIdx.x * blockDim.x + threadIdx.x;
    if (i < NGN) {
        g_rs_gg_src[i] = rsqrtf((float)max(g_cnt_gg_src[i], 1));
        g_rs_gg_dst[i] = rsqrtf((float)max(g_cnt_gg_dst[i], 1));
        g_rs_gd_src[i] = rsqrtf((float)max(g_cnt_gd_src[i], 1));
    }
    if (i < NDN) {
        g_rs_gd_dst[i] = rsqrtf((float)max(g_cnt_gd_dst[i], 1));
        g_rs_dd_src[i] = rsqrtf((float)max(g_cnt_dd_src[i], 1));
        g_rs_dd_dst[i] = rsqrtf((float)max(g_cnt_dd_dst[i], 1));
    }
}

// 4 independent single-block exclusive scans (one per CSR), one kernel with 4 blocks
__global__ void k_scan4() {
    const int* cnt; int* rp; int* fill; int n;
    if (blockIdx.x == 0)      { cnt = g_cnt_gg_dst; rp = g_rp_gg; fill = g_fill_gg; n = NGN; }
    else if (blockIdx.x == 1) { cnt = g_cnt_gd_src; rp = g_rp_dg; fill = g_fill_dg; n = NGN; }
    else if (blockIdx.x == 2) { cnt = g_cnt_gd_dst; rp = g_rp_gd; fill = g_fill_gd; n = NDN; }
    else                      { cnt = g_cnt_dd_dst; rp = g_rp_dd; fill = g_fill_dd; n = NDN; }
    __shared__ int ts[1024];
    const int t = threadIdx.x;
    const int C = (n + 1023) / 1024;
    int lo = t * C, hi = min((t + 1) * C, n);
    int s = 0;
    for (int i = lo; i < hi; i++) s += cnt[i];
    ts[t] = s;
    __syncthreads();
    for (int off = 1; off < 1024; off <<= 1) {
        int v = (t >= off) ? ts[t - off] : 0;
        __syncthreads();
        ts[t] += v;
        __syncthreads();
    }
    int run = ts[t] - s;  // exclusive prefix
    for (int i = lo; i < hi; i++) { rp[i] = run; fill[i] = run; run += cnt[i]; }
    if (t == 1023) rp[n] = ts[1023];
}

// one fused CSR-fill over all 3 relations
__global__ void k_scatter_all(const int* __restrict__ gg_s, const int* __restrict__ gg_d,
                              const int* __restrict__ gd_s, const int* __restrict__ gd_d,
                              const int* __restrict__ dd_s, const int* __restrict__ dd_d,
                              int ngg, int ngd, int ndd) {
    const int total = ngg + ngd + ndd;
    for (int i = blockIdx.x * blockDim.x + threadIdx.x; i < total; i += gridDim.x * blockDim.x) {
        if (i < ngg) {
            int r = gg_d[i];
            int p = atomicAdd(&g_fill_gg[r], 1);
            g_col_gg[p] = gg_s[i];
        } else if (i < ngg + ngd) {
            int j = i - ngg;
            int s = gd_s[j], d = gd_d[j];
            int p = atomicAdd(&g_fill_dg[s], 1);  // reversed relation disease->gene
            g_col_dg[p] = d;
            int q = atomicAdd(&g_fill_gd[d], 1);  // gene->disease
            g_col_gd[q] = s;
        } else {
            int j = i - ngg - ngd;
            int r = dd_d[j];
            int p = atomicAdd(&g_fill_dd[r], 1);
            g_col_dd[p] = dd_s[j];
        }
    }
}

// ---------------- dense transform: X[r] = (H[r] * scale[r]) @ W.T ----------------
// OutT: float or __half. TRANSW: use W[k*DOUT+o] (i.e. X = H @ W) instead of W[o*DIN+k].
template <int DIN, int DOUT, int RPW, bool TRANSW, typename OutT>
__global__ __launch_bounds__(256) void k_transform(
    const float* __restrict__ H, const float* __restrict__ scale,
    const float* __restrict__ W, OutT* __restrict__ X, int nrows)
{
    constexpr int CHUNK = (DIN < 64) ? DIN : 64;
    constexpr int NCH = DIN / CHUNK;
    constexpr int OPL = DOUT / 32;  // outputs per lane
    __shared__ float Wt[CHUNK][DOUT];       // k-major chunk
    __shared__ float hs[8][RPW][CHUNK];
    const int warp = threadIdx.x >> 5, lane = threadIdx.x & 31;
    const int rpb = 8 * RPW;
    for (int base = blockIdx.x * rpb; base < nrows; base += gridDim.x * rpb) {
        float acc[RPW][OPL];
        #pragma unroll
        for (int i = 0; i < RPW; i++)
            #pragma unroll
            for (int o = 0; o < OPL; o++) acc[i][o] = 0.f;
        for (int c = 0; c < NCH; c++) {
            __syncthreads();
            for (int i = threadIdx.x; i < CHUNK * DOUT; i += 256) {
                int k = i / DOUT, o = i - k * DOUT;
                Wt[k][o] = TRANSW ? W[(size_t)(c * CHUNK + k) * DOUT + o]
                                  : W[(size_t)o * DIN + c * CHUNK + k];
            }
            #pragma unroll
            for (int rr = 0; rr < RPW; rr++) {
                int r = base + warp * RPW + rr;
                if (r < nrows) {
                    float sc = scale ? scale[r] : 1.f;
                    #pragma unroll
                    for (int k = lane; k < CHUNK; k += 32)
                        hs[warp][rr][k] = H[(size_t)r * DIN + c * CHUNK + k] * sc;
                }
            }
            __syncthreads();
            #pragma unroll
            for (int k = 0; k < CHUNK; k++) {
                float w0 = Wt[k][lane];
                float w1 = (OPL > 1) ? Wt[k][(OPL > 1 ? lane + 32 : 0)] : 0.f;
                #pragma unroll
                for (int rr = 0; rr < RPW; rr++) {
                    float h = hs[warp][rr][k];
                    acc[rr][0] = fmaf(h, w0, acc[rr][0]);
                    if (OPL > 1) acc[rr][1] = fmaf(h, w1, acc[rr][1]);
                }
            }
        }
        #pragma unroll
        for (int rr = 0; rr < RPW; rr++) {
            int r = base + warp * RPW + rr;
            if (r < nrows) {
                if (sizeof(OutT) == 2) {
                    ((__half*)X)[(size_t)r * DOUT + lane] = __float2half_rn(acc[rr][0]);
                    if (OPL > 1)
                        ((__half*)X)[(size_t)r * DOUT + lane + 32] = __float2half_rn(acc[rr][1]);
                } else {
                    ((float*)X)[(size_t)r * DOUT + lane] = acc[rr][0];
                    if (OPL > 1)
                        ((float*)X)[(size_t)r * DOUT + lane + 32] = acc[rr][1];
                }
            }
        }
    }
}

// ------- fused dual-relation CSR aggregation (fp16 sources, fp32 accum) -------
// + dst-norm + bias + relu, warp per destination row
template <int DOUT>
__global__ __launch_bounds__(256) void k_agg(
    const int* __restrict__ rpA, const int* __restrict__ colA,
    const __half* __restrict__ xA, const float* __restrict__ ndA,
    const int* __restrict__ rpB, const int* __restrict__ colB,
    const __half* __restrict__ xB, const float* __restrict__ ndB,
    const float* __restrict__ bA, const float* __restrict__ bB,
    float* __restrict__ out, int nrows)
{
    const int v = blockIdx.x * (blockDim.x >> 5) + (threadIdx.x >> 5);
    const int lane = threadIdx.x & 31;
    if (v >= nrows) return;

    if (DOUT == 64) {
        const __half2* pA = (const __half2*)xA;
        const __half2* pB = (const __half2*)xB;
        float2 a = make_float2(0.f, 0.f), b = make_float2(0.f, 0.f);
        int s = rpA[v], e = rpA[v + 1], j = s;
        for (; j + 4 <= e; j += 4) {
            int u0 = colA[j], u1 = colA[j + 1], u2 = colA[j + 2], u3 = colA[j + 3];
            float2 t0 = __half22float2(pA[(size_t)u0 * 32 + lane]);
            float2 t1 = __half22float2(pA[(size_t)u1 * 32 + lane]);
            float2 t2 = __half22float2(pA[(size_t)u2 * 32 + lane]);
            float2 t3 = __half22float2(pA[(size_t)u3 * 32 + lane]);
            a.x += (t0.x + t1.x) + (t2.x + t3.x);
            a.y += (t0.y + t1.y) + (t2.y + t3.y);
        }
        for (; j < e; j++) {
            float2 t = __half22float2(pA[(size_t)colA[j] * 32 + lane]);
            a.x += t.x; a.y += t.y;
        }
        s = rpB[v]; e = rpB[v + 1]; j = s;
        for (; j + 4 <= e; j += 4) {
            int u0 = colB[j], u1 = colB[j + 1], u2 = colB[j + 2], u3 = colB[j + 3];
            float2 t0 = __half22float2(pB[(size_t)u0 * 32 + lane]);
            float2 t1 = __half22float2(pB[(size_t)u1 * 32 + lane]);
            float2 t2 = __half22float2(pB[(size_t)u2 * 32 + lane]);
            float2 t3 = __half22float2(pB[(size_t)u3 * 32 + lane]);
            b.x += (t0.x + t1.x) + (t2.x + t3.x);
            b.y += (t0.y + t1.y) + (t2.y + t3.y);
        }
        for (; j < e; j++) {
            float2 t = __half22float2(pB[(size_t)colB[j] * 32 + lane]);
            b.x += t.x; b.y += t.y;
        }
        float na = ndA[v], nb = ndB[v];
        float ox = na * a.x + nb * b.x + bA[lane * 2] + bB[lane * 2];
        float oy = na * a.y + nb * b.y + bA[lane * 2 + 1] + bB[lane * 2 + 1];
        ox = fmaxf(ox, 0.f); oy = fmaxf(oy, 0.f);
        *(float2*)(out + (size_t)v * 64 + lane * 2) = make_float2(ox, oy);
    } else {  // DOUT == 32
        float a = 0.f, b = 0.f;
        int s = rpA[v], e = rpA[v + 1], j = s;
        for (; j + 8 <= e; j += 8) {
            float t = 0.f;
            #pragma unroll
            for (int q = 0; q < 8; q++)
                t += __half2float(xA[(size_t)colA[j + q] * 32 + lane]);
            a += t;
        }
        for (; j < e; j++) a += __half2float(xA[(size_t)colA[j] * 32 + lane]);
        s = rpB[v]; e = rpB[v + 1]; j = s;
        for (; j + 8 <= e; j += 8) {
            float t = 0.f;
            #pragma unroll
            for (int q = 0; q < 8; q++)
                t += __half2float(xB[(size_t)colB[j + q] * 32 + lane]);
            b += t;
        }
        for (; j < e; j++) b += __half2float(xB[(size_t)colB[j] * 32 + lane]);
        float o = ndA[v] * a + ndB[v] * b + bA[lane] + bB[lane];
        out[(size_t)v * 32 + lane] = fmaxf(o, 0.f);
    }
}

// ---------------- final GEMM: C[M,N] = A[M,32] @ B[N,32]^T (fp32) ----------------
__global__ __launch_bounds__(256) void k_outgemm(
    const float* __restrict__ A, const float* __restrict__ B,
    float* __restrict__ C, int M, int N)
{
    __shared__ float As[32][128];
    __shared__ float Bs[32][128];
    const int m0 = blockIdx.y * 128, n0 = blockIdx.x * 128;
    const int tid = threadIdx.x;
    for (int i = tid; i < 128 * 8; i += 256) {
        int r = i >> 3, c4 = (i & 7) << 2;
        float4 v = make_float4(0.f, 0.f, 0.f, 0.f);
        if (m0 + r < M) v = *(const float4*)(A + (size_t)(m0 + r) * 32 + c4);
        As[c4 + 0][r] = v.x; As[c4 + 1][r] = v.y; As[c4 + 2][r] = v.z; As[c4 + 3][r] = v.w;
    }
    for (int i = tid; i < 128 * 8; i += 256) {
        int r = i >> 3, c4 = (i & 7) << 2;
        float4 v = make_float4(0.f, 0.f, 0.f, 0.f);
        if (n0 + r < N) v = *(const float4*)(B + (size_t)(n0 + r) * 32 + c4);
        Bs[c4 + 0][r] = v.x; Bs[c4 + 1][r] = v.y; Bs[c4 + 2][r] = v.z; Bs[c4 + 3][r] = v.w;
    }
    __syncthreads();
    const int tx = tid & 15, ty = tid >> 4;
    float acc[8][8];
    #pragma unroll
    for (int i = 0; i < 8; i++)
        #pragma unroll
        for (int j = 0; j < 8; j++) acc[i][j] = 0.f;
    #pragma unroll
    for (int k = 0; k < 32; k++) {
        float ar[8], br[8];
        *(float4*)(ar)     = *(const float4*)&As[k][ty * 8];
        *(float4*)(ar + 4) = *(const float4*)&As[k][ty * 8 + 4];
        *(float4*)(br)     = *(const float4*)&Bs[k][tx * 8];
        *(float4*)(br + 4) = *(const float4*)&Bs[k][tx * 8 + 4];
        #pragma unroll
        for (int i = 0; i < 8; i++)
            #pragma unroll
            for (int j = 0; j < 8; j++)
                acc[i][j] = fmaf(ar[i], br[j], acc[i][j]);
    }
    #pragma unroll
    for (int i = 0; i < 8; i++) {
        int m = m0 + ty * 8 + i;
        if (m >= M) continue;
        float* cp = C + (size_t)m * N + n0 + tx * 8;
        if (n0 + tx * 8 + 8 <= N) {
            *(float4*)cp       = make_float4(acc[i][0], acc[i][1], acc[i][2], acc[i][3]);
            *(float4*)(cp + 4) = make_float4(acc[i][4], acc[i][5], acc[i][6], acc[i][7]);
        } else {
            for (int j = 0; j < 8; j++)
                if (n0 + tx * 8 + j < N) cp[j] = acc[i][j];
        }
    }
}

// ---------------- launch ----------------
#define SYMP(var, T, sym) do { void* _p; cudaGetSymbolAddress(&_p, sym); var = (T*)_p; } while (0)

extern "C" void kernel_launch(void* const* d_in, const int* in_sizes, int n_in,
                              void* d_out, int out_size)
{
    const float* feat_g = (const float*)d_in[0];
    const float* feat_d = (const float*)d_in[1];
    const int* gg_src = (const int*)d_in[2];
    const int* gg_dst = (const int*)d_in[3];
    const int* gd_src = (const int*)d_in[4];
    const int* gd_dst = (const int*)d_in[5];
    const int* dd_src = (const int*)d_in[6];
    const int* dd_dst = (const int*)d_in[7];
    const float* Wg   = (const float*)d_in[8];
    const float* Wd   = (const float*)d_in[9];
    const float* W1   = (const float*)d_in[10];
    const float* b1   = (const float*)d_in[11];
    const float* W2   = (const float*)d_in[12];
    const float* b2   = (const float*)d_in[13];
    const float* Wout = (const float*)d_in[14];
    const int n_gg = in_sizes[2], n_gd = in_sizes[4], n_dd = in_sizes[6];

    int *rp_gg, *rp_dg, *rp_gd, *rp_dd;
    int *col_gg, *col_dg, *col_gd, *col_dd;
    float *rs_gg_src, *rs_gg_dst, *rs_gd_src, *rs_gd_dst, *rs_dd_src, *rs_dd_dst;
    float *hg, *hd, *og, *od, *yd;
    __half *xga, *xgb, *xda, *xdb;
    SYMP(rp_gg, int, g_rp_gg); SYMP(rp_dg, int, g_rp_dg);
    SYMP(rp_gd, int, g_rp_gd); SYMP(rp_dd, int, g_rp_dd);
    SYMP(col_gg, int, g_col_gg); SYMP(col_dg, int, g_col_dg);
    SYMP(col_gd, int, g_col_gd); SYMP(col_dd, int, g_col_dd);
    SYMP(rs_gg_src, float, g_rs_gg_src); SYMP(rs_gg_dst, float, g_rs_gg_dst);
    SYMP(rs_gd_src, float, g_rs_gd_src); SYMP(rs_gd_dst, float, g_rs_gd_dst);
    SYMP(rs_dd_src, float, g_rs_dd_src); SYMP(rs_dd_dst, float, g_rs_dd_dst);
    SYMP(hg, float, g_hg); SYMP(hd, float, g_hd);
    SYMP(og, float, g_og); SYMP(od, float, g_od); SYMP(yd, float, g_yd);
    SYMP(xga, __half, g_xga); SYMP(xgb, __half, g_xgb);
    SYMP(xda, __half, g_xda); SYMP(xdb, __half, g_xdb);

    // 1) degrees + CSR build (fused hist, fused scatter)
    k_zero_counts<<<(NGN + 255) / 256, 256>>>();
    k_hist_all<<<1480, 256>>>(gg_src, gg_dst, gd_src, gd_dst, dd_src, dd_dst,
                              n_gg, n_gd, n_dd);
    k_rsqrt<<<(NGN + 255) / 256, 256>>>();
    k_scan4<<<4, 1024>>>();
    k_scatter_all<<<1480, 256>>>(gg_src, gg_dst, gd_src, gd_dst, dd_src, dd_dst,
                                 n_gg, n_gd, n_dd);

    // 2) embeddings: hg = feat_gene @ Wg.T ; hd = feat_dis @ Wd.T (fp32)
    k_transform<512, 64, 4, false, float><<<(NGN + 31) / 32, 256>>>(feat_g, nullptr, Wg, hg, NGN);
    k_transform<512, 64, 4, false, float><<<(NDN + 31) / 32, 256>>>(feat_d, nullptr, Wd, hd, NDN);

    // 3) layer 1 (H1=64): pre-scale + pre-transform to fp16, fused aggregate (fp32 accum)
    k_transform<64, 64, 2, false, __half><<<(NGN + 15) / 16, 256>>>(hg, rs_gg_src, W1 + 0 * 64 * 64, xga, NGN);
    k_transform<64, 64, 2, false, __half><<<(NDN + 15) / 16, 256>>>(hd, rs_gd_dst, W1 + 2 * 64 * 64, xda, NDN);
    k_transform<64, 64, 2, false, __half><<<(NGN + 15) / 16, 256>>>(hg, rs_gd_src, W1 + 1 * 64 * 64, xgb, NGN);
    k_transform<64, 64, 2, false, __half><<<(NDN + 15) / 16, 256>>>(hd, rs_dd_src, W1 + 3 * 64 * 64, xdb, NDN);
    k_agg<64><<<(NGN + 7) / 8, 256>>>(rp_gg, col_gg, xga, rs_gg_dst,
                                      rp_dg, col_dg, xda, rs_gd_src,
                                      b1 + 0 * 64, b1 + 2 * 64, og, NGN);
    k_agg<64><<<(NDN + 7) / 8, 256>>>(rp_gd, col_gd, xgb, rs_gd_dst,
                                      rp_dd, col_dd, xdb, rs_dd_dst,
                                      b1 + 1 * 64, b1 + 3 * 64, od, NDN);

    // 4) layer 2 (H2=32): transform first (fp16), aggregate at 32-dim
    k_transform<64, 32, 2, false, __half><<<(NGN + 15) / 16, 256>>>(og, rs_gg_src, W2 + 0 * 32 * 64, xga, NGN);
    k_transform<64, 32, 2, false, __half><<<(NDN + 15) / 16, 256>>>(od, rs_gd_dst, W2 + 2 * 32 * 64, xda, NDN);
    k_transform<64, 32, 2, false, __half><<<(NGN + 15) / 16, 256>>>(og, rs_gd_src, W2 + 1 * 32 * 64, xgb, NGN);
    k_transform<64, 32, 2, false, __half><<<(NDN + 15) / 16, 256>>>(od, rs_dd_src, W2 + 3 * 32 * 64, xdb, NDN);
    k_agg<32><<<(NGN + 7) / 8, 256>>>(rp_gg, col_gg, xga, rs_gg_dst,
                                      rp_dg, col_dg, xda, rs_gd_src,
                                      b2 + 0 * 32, b2 + 2 * 32, hg, NGN);   // hg2 [NG,32]
    k_agg<32><<<(NDN + 7) / 8, 256>>>(rp_gd, col_gd, xgb, rs_gd_dst,
                                      rp_dd, col_dd, xdb, rs_dd_dst,
                                      b2 + 1 * 32, b2 + 3 * 32, hd, NDN);   // hd2 [ND,32]

    // 5) yd = hd2 @ Wout (5000 rows instead of 12331) ; out = hg2 @ yd^T
    k_transform<32, 32, 2, true, float><<<(NDN + 15) / 16, 256>>>(hd, nullptr, Wout, yd, NDN);
    dim3 grid((NDN + 127) / 128, (NGN + 127) / 128);
    k_outgemm<<<grid, 256>>>(hg, yd, (float*)d_out, NGN, NDN);
}

// round 5
// speedup vs baseline: 1.2315x; 1.1609x over previous
#include <cuda_runtime.h>
#include <cuda_fp16.h>
#include <math.h>
#include <stdint.h>

#define NGN 12331
#define NDN 5000
#define EGG 1000000
#define EGD 400000
#define EDD 100000

// ---------------- scratch (device globals; no allocation allowed) ----------------
__device__ int g_cnt_gg_src[NGN], g_cnt_gg_dst[NGN], g_cnt_gd_src[NGN];
__device__ int g_cnt_gd_dst[NDN], g_cnt_dd_src[NDN], g_cnt_dd_dst[NDN];
__device__ int g_rp_gg[NGN + 1], g_rp_dg[NGN + 1], g_rp_gd[NDN + 1], g_rp_dd[NDN + 1];
__device__ int g_fill_gg[NGN], g_fill_dg[NGN], g_fill_gd[NDN], g_fill_dd[NDN];
__device__ int g_col_gg[EGG], g_col_dg[EGD], g_col_gd[EGD], g_col_dd[EDD];
__device__ float g_rs_gg_src[NGN], g_rs_gg_dst[NGN], g_rs_gd_src[NGN];
__device__ float g_rs_gd_dst[NDN], g_rs_dd_src[NDN], g_rs_dd_dst[NDN];
__device__ float g_hg[NGN * 64], g_hd[NDN * 64];
__device__ __align__(256) __half g_xga[NGN * 64], g_xgb[NGN * 64];
__device__ __align__(256) __half g_xda[NDN * 64], g_xdb[NDN * 64];
__device__ __align__(256) __half g_ah[NGN * 32];
__device__ float g_og[NGN * 64], g_od[NDN * 64];

// ---------------- setup kernels ----------------
__global__ void k_zero_counts() {
    int i = blockIdx.x * blockDim.x + threadIdx.x;
    if (i < NGN) { g_cnt_gg_src[i] = 0; g_cnt_gg_dst[i] = 0; g_cnt_gd_src[i] = 0; }
    if (i < NDN) { g_cnt_gd_dst[i] = 0; g_cnt_dd_src[i] = 0; g_cnt_dd_dst[i] = 0; }
}

__global__ void k_hist_all(const int* __restrict__ gg_s, const int* __restrict__ gg_d,
                           const int* __restrict__ gd_s, const int* __restrict__ gd_d,
                           const int* __restrict__ dd_s, const int* __restrict__ dd_d,
                           int ngg, int ngd, int ndd) {
    const int total = ngg + ngd + ndd;
    for (int i = blockIdx.x * blockDim.x + threadIdx.x; i < total; i += gridDim.x * blockDim.x) {
        if (i < ngg) {
            atomicAdd(&g_cnt_gg_src[gg_s[i]], 1);
            atomicAdd(&g_cnt_gg_dst[gg_d[i]], 1);
        } else if (i < ngg + ngd) {
            int j = i - ngg;
            atomicAdd(&g_cnt_gd_src[gd_s[j]], 1);
            atomicAdd(&g_cnt_gd_dst[gd_d[j]], 1);
        } else {
            int j = i - ngg - ngd;
            atomicAdd(&g_cnt_dd_src[dd_s[j]], 1);
            atomicAdd(&g_cnt_dd_dst[dd_d[j]], 1);
        }
    }
}

__global__ void k_rsqrt() {
    int i = blockIdx.x * blockDim.x + threadIdx.x;
    if (i < NGN) {
        g_rs_gg_src[i] = rsqrtf((float)max(g_cnt_gg_src[i], 1));
        g_rs_gg_dst[i] = rsqrtf((float)max(g_cnt_gg_dst[i], 1));
        g_rs_gd_src[i] = rsqrtf((float)max(g_cnt_gd_src[i], 1));
    }
    if (i < NDN) {
        g_rs_gd_dst[i] = rsqrtf((float)max(g_cnt_gd_dst[i], 1));
        g_rs_dd_src[i] = rsqrtf((float)max(g_cnt_dd_src[i], 1));
        g_rs_dd_dst[i] = rsqrtf((float)max(g_cnt_dd_dst[i], 1));
    }
}

// 4 single-block exclusive scans, shfl-based (2 barriers instead of 20)
__global__ void k_scan4() {
    const int* cnt; int* rp; int* fill; int n;
    if (blockIdx.x == 0)      { cnt = g_cnt_gg_dst; rp = g_rp_gg; fill = g_fill_gg; n = NGN; }
    else if (blockIdx.x == 1) { cnt = g_cnt_gd_src; rp = g_rp_dg; fill = g_fill_dg; n = NGN; }
    else if (blockIdx.x == 2) { cnt = g_cnt_gd_dst; rp = g_rp_gd; fill = g_fill_gd; n = NDN; }
    else                      { cnt = g_cnt_dd_dst; rp = g_rp_dd; fill = g_fill_dd; n = NDN; }
    __shared__ int warp_tot[32];
    const int t = threadIdx.x;
    const int lane = t & 31, w = t >> 5;
    const int C = (n + 1023) / 1024;
    int lo = t * C, hi = min((t + 1) * C, n);
    int s = 0;
    for (int i = lo; i < hi; i++) s += cnt[i];
    int v = s;
    #pragma unroll
    for (int o = 1; o < 32; o <<= 1) {
        int u = __shfl_up_sync(0xFFFFFFFFu, v, o);
        if (lane >= o) v += u;
    }
    if (lane == 31) warp_tot[w] = v;
    __syncthreads();
    if (w == 0) {
        int x = warp_tot[lane];
        #pragma unroll
        for (int o = 1; o < 32; o <<= 1) {
            int u = __shfl_up_sync(0xFFFFFFFFu, x, o);
            if (lane >= o) x += u;
        }
        warp_tot[lane] = x;
    }
    __syncthreads();
    int run = v - s + (w > 0 ? warp_tot[w - 1] : 0);  // exclusive prefix
    for (int i = lo; i < hi; i++) { int c = cnt[i]; rp[i] = run; fill[i] = run; run += c; }
    if (t == 1023) rp[n] = run;
}

__global__ void k_scatter_all(const int* __restrict__ gg_s, const int* __restrict__ gg_d,
                              const int* __restrict__ gd_s, const int* __restrict__ gd_d,
                              const int* __restrict__ dd_s, const int* __restrict__ dd_d,
                              int ngg, int ngd, int ndd) {
    const int total = ngg + ngd + ndd;
    for (int i = blockIdx.x * blockDim.x + threadIdx.x; i < total; i += gridDim.x * blockDim.x) {
        if (i < ngg) {
            int r = gg_d[i];
            int p = atomicAdd(&g_fill_gg[r], 1);
            g_col_gg[p] = gg_s[i];
        } else if (i < ngg + ngd) {
            int j = i - ngg;
            int s = gd_s[j], d = gd_d[j];
            int p = atomicAdd(&g_fill_dg[s], 1);  // reversed: disease->gene
            g_col_dg[p] = d;
            int q = atomicAdd(&g_fill_gd[d], 1);  // gene->disease
            g_col_gd[q] = s;
        } else {
            int j = i - ngg - ngd;
            int r = dd_d[j];
            int p = atomicAdd(&g_fill_dd[r], 1);
            g_col_dd[p] = dd_s[j];
        }
    }
}

// ---------------- single dense transform: X[r] = (H[r]*scale[r]) @ W(.T) ----------------
template <int DIN, int DOUT, int RPW, bool TRANSW, typename OutT>
__global__ __launch_bounds__(256) void k_transform(
    const float* __restrict__ H, const float* __restrict__ scale,
    const float* __restrict__ W, OutT* __restrict__ X, int nrows)
{
    constexpr int CHUNK = (DIN < 64) ? DIN : 64;
    constexpr int NCH = DIN / CHUNK;
    constexpr int OPL = DOUT / 32;
    __shared__ float Wt[CHUNK][DOUT];
    __shared__ float hs[8][RPW][CHUNK];
    const int warp = threadIdx.x >> 5, lane = threadIdx.x & 31;
    const int rpb = 8 * RPW;
    for (int base = blockIdx.x * rpb; base < nrows; base += gridDim.x * rpb) {
        float acc[RPW][OPL];
        #pragma unroll
        for (int i = 0; i < RPW; i++)
            #pragma unroll
            for (int o = 0; o < OPL; o++) acc[i][o] = 0.f;
        for (int c = 0; c < NCH; c++) {
            __syncthreads();
            for (int i = threadIdx.x; i < CHUNK * DOUT; i += 256) {
                int k = i / DOUT, o = i - k * DOUT;
                Wt[k][o] = TRANSW ? W[(size_t)(c * CHUNK + k) * DOUT + o]
                                  : W[(size_t)o * DIN + c * CHUNK + k];
            }
            #pragma unroll
            for (int rr = 0; rr < RPW; rr++) {
                int r = base + warp * RPW + rr;
                if (r < nrows) {
                    float sc = scale ? scale[r] : 1.f;
                    #pragma unroll
                    for (int k = lane; k < CHUNK; k += 32)
                        hs[warp][rr][k] = H[(size_t)r * DIN + c * CHUNK + k] * sc;
                }
            }
            __syncthreads();
            #pragma unroll
            for (int k = 0; k < CHUNK; k++) {
                float w0 = Wt[k][lane];
                float w1 = (OPL > 1) ? Wt[k][(OPL > 1 ? lane + 32 : 0)] : 0.f;
                #pragma unroll
                for (int rr = 0; rr < RPW; rr++) {
                    float h = hs[warp][rr][k];
                    acc[rr][0] = fmaf(h, w0, acc[rr][0]);
                    if (OPL > 1) acc[rr][1] = fmaf(h, w1, acc[rr][1]);
                }
            }
        }
        #pragma unroll
        for (int rr = 0; rr < RPW; rr++) {
            int r = base + warp * RPW + rr;
            if (r < nrows) {
                if (sizeof(OutT) == 2) {
                    ((__half*)X)[(size_t)r * DOUT + lane] = __float2half_rn(acc[rr][0]);
                    if (OPL > 1)
                        ((__half*)X)[(size_t)r * DOUT + lane + 32] = __float2half_rn(acc[rr][1]);
                } else {
                    ((float*)X)[(size_t)r * DOUT + lane] = acc[rr][0];
                    if (OPL > 1)
                        ((float*)X)[(size_t)r * DOUT + lane + 32] = acc[rr][1];
                }
            }
        }
    }
}

// -------- fused dual-relation transform: read H once, two W's, post-scale, fp16 out --------
// XA[r] = half( scA[r] * (H[r] @ WA.T) ), XB[r] = half( scB[r] * (H[r] @ WB.T) )
template <int DOUT>
__global__ __launch_bounds__(256) void k_transform2(
    const float* __restrict__ H,
    const float* __restrict__ scA, const float* __restrict__ WA,
    const float* __restrict__ scB, const float* __restrict__ WB,
    __half* __restrict__ XA, __half* __restrict__ XB, int nrows)
{
    constexpr int RPW = 2;
    constexpr int OPL = DOUT / 32;
    __shared__ float WtA[64][DOUT];
    __shared__ float WtB[64][DOUT];
    __shared__ float hs[8][RPW][64];
    const int warp = threadIdx.x >> 5, lane = threadIdx.x & 31;
    const int rpb = 8 * RPW;
    // load both weight chunks once (k-major)
    for (int i = threadIdx.x; i < 64 * DOUT; i += 256) {
        int k = i / DOUT, o = i - k * DOUT;
        WtA[k][o] = WA[(size_t)o * 64 + k];
        WtB[k][o] = WB[(size_t)o * 64 + k];
    }
    for (int base = blockIdx.x * rpb; base < nrows; base += gridDim.x * rpb) {
        float aA[RPW][OPL], aB[RPW][OPL];
        #pragma unroll
        for (int i = 0; i < RPW; i++)
            #pragma unroll
            for (int o = 0; o < OPL; o++) { aA[i][o] = 0.f; aB[i][o] = 0.f; }
        __syncthreads();
        #pragma unroll
        for (int rr = 0; rr < RPW; rr++) {
            int r = base + warp * RPW + rr;
            if (r < nrows)
                #pragma unroll
                for (int k = lane; k < 64; k += 32)
                    hs[warp][rr][k] = H[(size_t)r * 64 + k];
        }
        __syncthreads();
        #pragma unroll
        for (int k = 0; k < 64; k++) {
            float wa0 = WtA[k][lane], wb0 = WtB[k][lane];
            float wa1 = (OPL > 1) ? WtA[k][(OPL > 1 ? lane + 32 : 0)] : 0.f;
            float wb1 = (OPL > 1) ? WtB[k][(OPL > 1 ? lane + 32 : 0)] : 0.f;
            #pragma unroll
            for (int rr = 0; rr < RPW; rr++) {
                float h = hs[warp][rr][k];
                aA[rr][0] = fmaf(h, wa0, aA[rr][0]);
                aB[rr][0] = fmaf(h, wb0, aB[rr][0]);
                if (OPL > 1) {
                    aA[rr][1] = fmaf(h, wa1, aA[rr][1]);
                    aB[rr][1] = fmaf(h, wb1, aB[rr][1]);
                }
            }
        }
        #pragma unroll
        for (int rr = 0; rr < RPW; rr++) {
            int r = base + warp * RPW + rr;
            if (r < nrows) {
                float sA = scA[r], sB = scB[r];
                XA[(size_t)r * DOUT + lane] = __float2half_rn(aA[rr][0] * sA);
                XB[(size_t)r * DOUT + lane] = __float2half_rn(aB[rr][0] * sB);
                if (OPL > 1) {
                    XA[(size_t)r * DOUT + lane + 32] = __float2half_rn(aA[rr][1] * sA);
                    XB[(size_t)r * DOUT + lane + 32] = __float2half_rn(aB[rr][1] * sB);
                }
            }
        }
    }
}

// ------- fused dual-relation CSR aggregation (fp16 sources, fp32 accum) -------
template <int DOUT, typename OutT>
__global__ __launch_bounds__(256) void k_agg(
    const int* __restrict__ rpA, const int* __restrict__ colA,
    const __half* __restrict__ xA, const float* __restrict__ ndA,
    const int* __restrict__ rpB, const int* __restrict__ colB,
    const __half* __restrict__ xB, const float* __restrict__ ndB,
    const float* __restrict__ bA, const float* __restrict__ bB,
    OutT* __restrict__ out, int nrows)
{
    const int v = blockIdx.x * (blockDim.x >> 5) + (threadIdx.x >> 5);
    const int lane = threadIdx.x & 31;
    if (v >= nrows) return;

    if (DOUT == 64) {
        const __half2* pA = (const __half2*)xA;
        const __half2* pB = (const __half2*)xB;
        float2 a = make_float2(0.f, 0.f), b = make_float2(0.f, 0.f);
        int s = rpA[v], e = rpA[v + 1], j = s;
        for (; j + 4 <= e; j += 4) {
            int u0 = colA[j], u1 = colA[j + 1], u2 = colA[j + 2], u3 = colA[j + 3];
            float2 t0 = __half22float2(pA[(size_t)u0 * 32 + lane]);
            float2 t1 = __half22float2(pA[(size_t)u1 * 32 + lane]);
            float2 t2 = __half22float2(pA[(size_t)u2 * 32 + lane]);
            float2 t3 = __half22float2(pA[(size_t)u3 * 32 + lane]);
            a.x += (t0.x + t1.x) + (t2.x + t3.x);
            a.y += (t0.y + t1.y) + (t2.y + t3.y);
        }
        for (; j < e; j++) {
            float2 t = __half22float2(pA[(size_t)colA[j] * 32 + lane]);
            a.x += t.x; a.y += t.y;
        }
        s = rpB[v]; e = rpB[v + 1]; j = s;
        for (; j + 4 <= e; j += 4) {
            int u0 = colB[j], u1 = colB[j + 1], u2 = colB[j + 2], u3 = colB[j + 3];
            float2 t0 = __half22float2(pB[(size_t)u0 * 32 + lane]);
            float2 t1 = __half22float2(pB[(size_t)u1 * 32 + lane]);
            float2 t2 = __half22float2(pB[(size_t)u2 * 32 + lane]);
            float2 t3 = __half22float2(pB[(size_t)u3 * 32 + lane]);
            b.x += (t0.x + t1.x) + (t2.x + t3.x);
            b.y += (t0.y + t1.y) + (t2.y + t3.y);
        }
        for (; j < e; j++) {
            float2 t = __half22float2(pB[(size_t)colB[j] * 32 + lane]);
            b.x += t.x; b.y += t.y;
        }
        float na = ndA[v], nb = ndB[v];
        float ox = na * a.x + nb * b.x + bA[lane * 2] + bB[lane * 2];
        float oy = na * a.y + nb * b.y + bA[lane * 2 + 1] + bB[lane * 2 + 1];
        ox = fmaxf(ox, 0.f); oy = fmaxf(oy, 0.f);
        *(float2*)((float*)out + (size_t)v * 64 + lane * 2) = make_float2(ox, oy);
    } else {  // DOUT == 32
        float a = 0.f, b = 0.f;
        int s = rpA[v], e = rpA[v + 1], j = s;
        for (; j + 8 <= e; j += 8) {
            float t = 0.f;
            #pragma unroll
            for (int q = 0; q < 8; q++)
                t += __half2float(xA[(size_t)colA[j + q] * 32 + lane]);
            a += t;
        }
        for (; j < e; j++) a += __half2float(xA[(size_t)colA[j] * 32 + lane]);
        s = rpB[v]; e = rpB[v + 1]; j = s;
        for (; j + 8 <= e; j += 8) {
            float t = 0.f;
            #pragma unroll
            for (int q = 0; q < 8; q++)
                t += __half2float(xB[(size_t)colB[j + q] * 32 + lane]);
            b += t;
        }
        for (; j < e; j++) b += __half2float(xB[(size_t)colB[j] * 32 + lane]);
        float o = ndA[v] * a + ndB[v] * b + bA[lane] + bB[lane];
        o = fmaxf(o, 0.f);
        if (sizeof(OutT) == 2)
            ((__half*)out)[(size_t)v * 32 + lane] = __float2half_rn(o);
        else
            ((float*)out)[(size_t)v * 32 + lane] = o;
    }
}

// -------- tensor-core final GEMM: C[M,N] = A[M,32] @ B[N,32]^T, fp16 in, fp32 acc --------
// block tile 128x64, 8 warps (2x4), warp tile 64x16, mma.m16n8k16
__global__ __launch_bounds__(256) void k_outgemm_mma(
    const __half* __restrict__ A, const __half* __restrict__ B,
    float* __restrict__ C, int M, int N)
{
    __shared__ float cs[128][68];   // +4 pad: float4-aligned rows, conflict-light
    const int warp = threadIdx.x >> 5, lane = threadIdx.x & 31;
    const int wm = warp >> 2;            // 0..1 -> 64 rows each
    const int wn = warp & 3;             // 0..3 -> 16 cols each
    const int mb = blockIdx.y * 128;
    const int nb = blockIdx.x * 64;
    const int m0 = mb + wm * 64;
    const int n0 = nb + wn * 16;
    const int g = lane >> 2;             // 0..7
    const int t = lane & 3;              // 0..3

    float acc[4][2][4];
    #pragma unroll
    for (int mt = 0; mt < 4; mt++)
        #pragma unroll
        for (int nt = 0; nt < 2; nt++)
            #pragma unroll
            for (int q = 0; q < 4; q++) acc[mt][nt][q] = 0.f;

    #pragma unroll
    for (int kt = 0; kt < 2; kt++) {
        const int kb = kt * 16;
        uint32_t af[4][4];
        #pragma unroll
        for (int mt = 0; mt < 4; mt++) {
            int r0 = m0 + mt * 16 + g;
            int r1 = r0 + 8;
            af[mt][0] = (r0 < M) ? *(const uint32_t*)(A + (size_t)r0 * 32 + kb + 2 * t) : 0u;
            af[mt][1] = (r1 < M) ? *(const uint32_t*)(A + (size_t)r1 * 32 + kb + 2 * t) : 0u;
            af[mt][2] = (r0 < M) ? *(const uint32_t*)(A + (size_t)r0 * 32 + kb + 8 + 2 * t) : 0u;
            af[mt][3] = (r1 < M) ? *(const uint32_t*)(A + (size_t)r1 * 32 + kb + 8 + 2 * t) : 0u;
        }
        #pragma unroll
        for (int nt = 0; nt < 2; nt++) {
            int c = n0 + nt * 8 + g;
            uint32_t bf0 = (c < N) ? *(const uint32_t*)(B + (size_t)c * 32 + kb + 2 * t) : 0u;
            uint32_t bf1 = (c < N) ? *(const uint32_t*)(B + (size_t)c * 32 + kb + 8 + 2 * t) : 0u;
            #pragma unroll
            for (int mt = 0; mt < 4; mt++) {
                asm volatile(
                    "mma.sync.aligned.m16n8k16.row.col.f32.f16.f16.f32 "
                    "{%0,%1,%2,%3}, {%4,%5,%6,%7}, {%8,%9}, {%0,%1,%2,%3};"
                    : "+f"(acc[mt][nt][0]), "+f"(acc[mt][nt][1]),
                      "+f"(acc[mt][nt][2]), "+f"(acc[mt][nt][3])
                    : "r"(af[mt][0]), "r"(af[mt][1]), "r"(af[mt][2]), "r"(af[mt][3]),
                      "r"(bf0), "r"(bf1));
            }
        }
    }

    // stage to smem, then coalesced store
    #pragma unroll
    for (int mt = 0; mt < 4; mt++) {
        int rr = wm * 64 + mt * 16 + g;
        #pragma unroll
        for (int nt = 0; nt < 2; nt++) {
            int cc = wn * 16 + nt * 8 + 2 * t;
            cs[rr][cc]         = acc[mt][nt][0];
            cs[rr][cc + 1]     = acc[mt][nt][1];
            cs[rr + 8][cc]     = acc[mt][nt][2];
            cs[rr + 8][cc + 1] = acc[mt][nt][3];
        }
    }
    __syncthreads();
    for (int i = threadIdx.x; i < 128 * 16; i += 256) {
        int row = i >> 4, c4 = (i & 15) << 2;
        int m = mb + row, n = nb + c4;
        if (m >= M) continue;
        if (n + 3 < N) {
            *(float4*)(C + (size_t)m * N + n) =
                make_float4(cs[row][c4], cs[row][c4 + 1], cs[row][c4 + 2], cs[row][c4 + 3]);
        } else {
            for (int q = 0; q < 4; q++)
                if (n + q < N) C[(size_t)m * N + n + q] = cs[row][c4 + q];
        }
    }
}

// ---------------- launch ----------------
#define SYMP(var, T, sym) do { void* _p; cudaGetSymbolAddress(&_p, sym); var = (T*)_p; } while (0)

extern "C" void kernel_launch(void* const* d_in, const int* in_sizes, int n_in,
                              void* d_out, int out_size)
{
    const float* feat_g = (const float*)d_in[0];
    const float* feat_d = (const float*)d_in[1];
    const int* gg_src = (const int*)d_in[2];
    const int* gg_dst = (const int*)d_in[3];
    const int* gd_src = (const int*)d_in[4];
    const int* gd_dst = (const int*)d_in[5];
    const int* dd_src = (const int*)d_in[6];
    const int* dd_dst = (const int*)d_in[7];
    const float* Wg   = (const float*)d_in[8];
    const float* Wd   = (const float*)d_in[9];
    const float* W1   = (const float*)d_in[10];
    const float* b1   = (const float*)d_in[11];
    const float* W2   = (const float*)d_in[12];
    const float* b2   = (const float*)d_in[13];
    const float* Wout = (const float*)d_in[14];
    const int n_gg = in_sizes[2], n_gd = in_sizes[4], n_dd = in_sizes[6];

    int *rp_gg, *rp_dg, *rp_gd, *rp_dd;
    int *col_gg, *col_dg, *col_gd, *col_dd;
    float *rs_gg_src, *rs_gg_dst, *rs_gd_src, *rs_gd_dst, *rs_dd_src, *rs_dd_dst;
    float *hg, *hd, *og, *od;
    __half *xga, *xgb, *xda, *xdb, *ah, *bh;
    SYMP(rp_gg, int, g_rp_gg); SYMP(rp_dg, int, g_rp_dg);
    SYMP(rp_gd, int, g_rp_gd); SYMP(rp_dd, int, g_rp_dd);
    SYMP(col_gg, int, g_col_gg); SYMP(col_dg, int, g_col_dg);
    SYMP(col_gd, int, g_col_gd); SYMP(col_dd, int, g_col_dd);
    SYMP(rs_gg_src, float, g_rs_gg_src); SYMP(rs_gg_dst, float, g_rs_gg_dst);
    SYMP(rs_gd_src, float, g_rs_gd_src); SYMP(rs_gd_dst, float, g_rs_gd_dst);
    SYMP(rs_dd_src, float, g_rs_dd_src); SYMP(rs_dd_dst, float, g_rs_dd_dst);
    SYMP(hg, float, g_hg); SYMP(hd, float, g_hd);
    SYMP(og, float, g_og); SYMP(od, float, g_od);
    SYMP(xga, __half, g_xga); SYMP(xgb, __half, g_xgb);
    SYMP(xda, __half, g_xda); SYMP(xdb, __half, g_xdb);
    SYMP(ah, __half, g_ah);
    bh = xda;  // free at GEMM time; reuse as B fp16 buffer

    // 1) degrees + CSR build
    k_zero_counts<<<(NGN + 255) / 256, 256>>>();
    k_hist_all<<<1480, 256>>>(gg_src, gg_dst, gd_src, gd_dst, dd_src, dd_dst,
                              n_gg, n_gd, n_dd);
    k_rsqrt<<<(NGN + 255) / 256, 256>>>();
    k_scan4<<<4, 1024>>>();
    k_scatter_all<<<1480, 256>>>(gg_src, gg_dst, gd_src, gd_dst, dd_src, dd_dst,
                                 n_gg, n_gd, n_dd);

    // 2) embeddings (fp32)
    k_transform<512, 64, 4, false, float><<<(NGN + 31) / 32, 256>>>(feat_g, nullptr, Wg, hg, NGN);
    k_transform<512, 64, 4, false, float><<<(NDN + 31) / 32, 256>>>(feat_d, nullptr, Wd, hd, NDN);

    // 3) layer 1: fused dual transforms (fp16 out), fused aggregate
    k_transform2<64><<<(NGN + 15) / 16, 256>>>(hg, rs_gg_src, W1 + 0 * 64 * 64,
                                               rs_gd_src, W1 + 1 * 64 * 64, xga, xgb, NGN);
    k_transform2<64><<<(NDN + 15) / 16, 256>>>(hd, rs_gd_dst, W1 + 2 * 64 * 64,
                                               rs_dd_src, W1 + 3 * 64 * 64, xda, xdb, NDN);
    k_agg<64, float><<<(NGN + 7) / 8, 256>>>(rp_gg, col_gg, xga, rs_gg_dst,
                                             rp_dg, col_dg, xda, rs_gd_src,
                                             b1 + 0 * 64, b1 + 2 * 64, og, NGN);
    k_agg<64, float><<<(NDN + 7) / 8, 256>>>(rp_gd, col_gd, xgb, rs_gd_dst,
                                             rp_dd, col_dd, xdb, rs_dd_dst,
                                             b1 + 1 * 64, b1 + 3 * 64, od, NDN);

    // 4) layer 2: fused dual transforms, aggregate at 32-dim
    k_transform2<32><<<(NGN + 15) / 16, 256>>>(og, rs_gg_src, W2 + 0 * 32 * 64,
                                               rs_gd_src, W2 + 1 * 32 * 64, xga, xgb, NGN);
    k_transform2<32><<<(NDN + 15) / 16, 256>>>(od, rs_gd_dst, W2 + 2 * 32 * 64,
                                               rs_dd_src, W2 + 3 * 32 * 64, xda, xdb, NDN);
    k_agg<32, __half><<<(NGN + 7) / 8, 256>>>(rp_gg, col_gg, xga, rs_gg_dst,
                                              rp_dg, col_dg, xda, rs_gd_src,
                                              b2 + 0 * 32, b2 + 2 * 32, ah, NGN);   // hg2 fp16
    k_agg<32, float><<<(NDN + 7) / 8, 256>>>(rp_gd, col_gd, xgb, rs_gd_dst,
                                             rp_dd, col_dd, xdb, rs_dd_dst,
                                             b2 + 1 * 32, b2 + 3 * 32, hd, NDN);    // hd2 fp32

    // 5) bh = hd2 @ Wout (fp16) ; out = ah @ bh^T via tensor cores
    k_transform<32, 32, 2, true, __half><<<(NDN + 15) / 16, 256>>>(hd, nullptr, Wout, bh, NDN);
    dim3 grid((NDN + 63) / 64, (NGN + 127) / 128);
    k_outgemm_mma<<<grid, 256>>>(ah, bh, (float*)d_out, NGN, NDN);
}

// round 7
// speedup vs baseline: 1.3486x; 1.0950x over previous
#include <cuda_runtime.h>
#include <cuda_fp16.h>
#include <math.h>
#include <stdint.h>

#define NGN 12331
#define NDN 5000
#define EGG 1000000
#define EGD 400000
#define EDD 100000

// ---------------- scratch (device globals; no allocation allowed) ----------------
__device__ int g_cnt_gg_src[NGN], g_cnt_gg_dst[NGN], g_cnt_gd_src[NGN];
__device__ int g_cnt_gd_dst[NDN], g_cnt_dd_src[NDN], g_cnt_dd_dst[NDN];
__device__ int g_rp_gg[NGN + 1], g_rp_dg[NGN + 1], g_rp_gd[NDN + 1], g_rp_dd[NDN + 1];
__device__ int g_fill_gg[NGN], g_fill_dg[NGN], g_fill_gd[NDN], g_fill_dd[NDN];
__device__ int g_col_gg[EGG], g_col_dg[EGD], g_col_gd[EGD], g_col_dd[EDD];
__device__ float g_rs_gg_src[NGN], g_rs_gg_dst[NGN], g_rs_gd_src[NGN];
__device__ float g_rs_gd_dst[NDN], g_rs_dd_src[NDN], g_rs_dd_dst[NDN];
__device__ __align__(256) float g_hg[NGN * 64];
__device__ __align__(256) float g_hd[NDN * 64];
__device__ __align__(256) __half g_xga[NGN * 64], g_xgb[NGN * 64];
__device__ __align__(256) __half g_xda[NDN * 64], g_xdb[NDN * 64];
__device__ __align__(256) __half g_ah[NGN * 32];
__device__ __align__(256) float g_og[NGN * 64];
__device__ __align__(256) float g_od[NDN * 64];

// ---------------- setup kernels ----------------
__global__ void k_zero_counts() {
    int i = blockIdx.x * blockDim.x + threadIdx.x;
    if (i < NGN) { g_cnt_gg_src[i] = 0; g_cnt_gg_dst[i] = 0; g_cnt_gd_src[i] = 0; }
    if (i < NDN) { g_cnt_gd_dst[i] = 0; g_cnt_dd_src[i] = 0; g_cnt_dd_dst[i] = 0; }
}

__global__ void k_hist_all(const int* __restrict__ gg_s, const int* __restrict__ gg_d,
                           const int* __restrict__ gd_s, const int* __restrict__ gd_d,
                           const int* __restrict__ dd_s, const int* __restrict__ dd_d,
                           int ngg, int ngd, int ndd) {
    const int total = ngg + ngd + ndd;
    for (int i = blockIdx.x * blockDim.x + threadIdx.x; i < total; i += gridDim.x * blockDim.x) {
        if (i < ngg) {
            atomicAdd(&g_cnt_gg_src[gg_s[i]], 1);
            atomicAdd(&g_cnt_gg_dst[gg_d[i]], 1);
        } else if (i < ngg + ngd) {
            int j = i - ngg;
            atomicAdd(&g_cnt_gd_src[gd_s[j]], 1);
            atomicAdd(&g_cnt_gd_dst[gd_d[j]], 1);
        } else {
            int j = i - ngg - ngd;
            atomicAdd(&g_cnt_dd_src[dd_s[j]], 1);
            atomicAdd(&g_cnt_dd_dst[dd_d[j]], 1);
        }
    }
}

// blocks 0..3: 4 single-block exclusive scans; blocks 4+: rsqrt of all degree arrays
__global__ void k_setup2() {
    __shared__ int warp_tot[32];
    if (blockIdx.x >= 4) {
        int i = (blockIdx.x - 4) * 1024 + threadIdx.x;
        if (i < NGN) {
            g_rs_gg_src[i] = rsqrtf((float)max(g_cnt_gg_src[i], 1));
            g_rs_gg_dst[i] = rsqrtf((float)max(g_cnt_gg_dst[i], 1));
            g_rs_gd_src[i] = rsqrtf((float)max(g_cnt_gd_src[i], 1));
        }
        if (i < NDN) {
            g_rs_gd_dst[i] = rsqrtf((float)max(g_cnt_gd_dst[i], 1));
            g_rs_dd_src[i] = rsqrtf((float)max(g_cnt_dd_src[i], 1));
            g_rs_dd_dst[i] = rsqrtf((float)max(g_cnt_dd_dst[i], 1));
        }
        return;
    }
    const int* cnt; int* rp; int* fill; int n;
    if (blockIdx.x == 0)      { cnt = g_cnt_gg_dst; rp = g_rp_gg; fill = g_fill_gg; n = NGN; }
    else if (blockIdx.x == 1) { cnt = g_cnt_gd_src; rp = g_rp_dg; fill = g_fill_dg; n = NGN; }
    else if (blockIdx.x == 2) { cnt = g_cnt_gd_dst; rp = g_rp_gd; fill = g_fill_gd; n = NDN; }
    else                      { cnt = g_cnt_dd_dst; rp = g_rp_dd; fill = g_fill_dd; n = NDN; }
    const int t = threadIdx.x;
    const int lane = t & 31, w = t >> 5;
    const int C = (n + 1023) / 1024;
    int lo = t * C, hi = min((t + 1) * C, n);
    int s = 0;
    for (int i = lo; i < hi; i++) s += cnt[i];
    int v = s;
    #pragma unroll
    for (int o = 1; o < 32; o <<= 1) {
        int u = __shfl_up_sync(0xFFFFFFFFu, v, o);
        if (lane >= o) v += u;
    }
    if (lane == 31) warp_tot[w] = v;
    __syncthreads();
    if (w == 0) {
        int x = warp_tot[lane];
        #pragma unroll
        for (int o = 1; o < 32; o <<= 1) {
            int u = __shfl_up_sync(0xFFFFFFFFu, x, o);
            if (lane >= o) x += u;
        }
        warp_tot[lane] = x;
    }
    __syncthreads();
    int run = v - s + (w > 0 ? warp_tot[w - 1] : 0);  // exclusive prefix
    for (int i = lo; i < hi; i++) { int c = cnt[i]; rp[i] = run; fill[i] = run; run += c; }
    if (t == 1023) rp[n] = run;
}

__global__ void k_scatter_all(const int* __restrict__ gg_s, const int* __restrict__ gg_d,
                              const int* __restrict__ gd_s, const int* __restrict__ gd_d,
                              const int* __restrict__ dd_s, const int* __restrict__ dd_d,
                              int ngg, int ngd, int ndd) {
    const int total = ngg + ngd + ndd;
    for (int i = blockIdx.x * blockDim.x + threadIdx.x; i < total; i += gridDim.x * blockDim.x) {
        if (i < ngg) {
            int r = gg_d[i];
            int p = atomicAdd(&g_fill_gg[r], 1);
            g_col_gg[p] = gg_s[i];
        } else if (i < ngg + ngd) {
            int j = i - ngg;
            int s = gd_s[j], d = gd_d[j];
            int p = atomicAdd(&g_fill_dg[s], 1);  // reversed: disease->gene
            g_col_dg[p] = d;
            int q = atomicAdd(&g_fill_gd[d], 1);  // gene->disease
            g_col_gd[q] = s;
        } else {
            int j = i - ngg - ngd;
            int r = dd_d[j];
            int p = atomicAdd(&g_fill_dd[r], 1);
            g_col_dd[p] = dd_s[j];
        }
    }
}

// ---------------- embeddings (both node types in one launch): H = F @ W.T ----------------
__global__ __launch_bounds__(256) void k_embed_pair(
    const float* __restrict__ Fg, const float* __restrict__ Wg, float* __restrict__ Hg, int ng,
    const float* __restrict__ Fd, const float* __restrict__ Wd, float* __restrict__ Hd, int nd,
    int gblocks)
{
    constexpr int RPW = 4;
    __shared__ float Wt[64][64];
    __shared__ float hs[8][RPW][64];
    const float *F, *W; float* H; int n, bid;
    if (blockIdx.x < gblocks) { F = Fg; W = Wg; H = Hg; n = ng; bid = blockIdx.x; }
    else                      { F = Fd; W = Wd; H = Hd; n = nd; bid = blockIdx.x - gblocks; }
    const int warp = threadIdx.x >> 5, lane = threadIdx.x & 31;
    const int base = bid * 8 * RPW;
    float acc[RPW][2];
    #pragma unroll
    for (int i = 0; i < RPW; i++) { acc[i][0] = 0.f; acc[i][1] = 0.f; }
    for (int c = 0; c < 8; c++) {
        __syncthreads();
        for (int i = threadIdx.x; i < 64 * 64; i += 256) {
            int k = i >> 6, o = i & 63;
            Wt[k][o] = W[(size_t)o * 512 + c * 64 + k];
        }
        #pragma unroll
        for (int rr = 0; rr < RPW; rr++) {
            int r = base + warp * RPW + rr;
            if (r < n) {
                hs[warp][rr][lane]      = F[(size_t)r * 512 + c * 64 + lane];
                hs[warp][rr][lane + 32] = F[(size_t)r * 512 + c * 64 + lane + 32];
            }
        }
        __syncthreads();
        #pragma unroll
        for (int k = 0; k < 64; k++) {
            float w0 = Wt[k][lane], w1 = Wt[k][lane + 32];
            #pragma unroll
            for (int rr = 0; rr < RPW; rr++) {
                float h = hs[warp][rr][k];
                acc[rr][0] = fmaf(h, w0, acc[rr][0]);
                acc[rr][1] = fmaf(h, w1, acc[rr][1]);
            }
        }
    }
    #pragma unroll
    for (int rr = 0; rr < RPW; rr++) {
        int r = base + warp * RPW + rr;
        if (r < n) {
            H[(size_t)r * 64 + lane]      = acc[rr][0];
            H[(size_t)r * 64 + lane + 32] = acc[rr][1];
        }
    }
}

// -------- fused dual-relation transform, both node types in one launch, fp16 out --------
// XA[r] = half( scA[r] * (H[r] @ WA.T) ), XB[r] = half( scB[r] * (H[r] @ WB.T) )
template <int DOUT>
__global__ __launch_bounds__(256) void k_t2_pair(
    const float* __restrict__ Hg,
    const float* __restrict__ sGA, const float* __restrict__ WGA,
    const float* __restrict__ sGB, const float* __restrict__ WGB,
    __half* __restrict__ XGA, __half* __restrict__ XGB, int ng,
    const float* __restrict__ Hd,
    const float* __restrict__ sDA, const float* __restrict__ WDA,
    const float* __restrict__ sDB, const float* __restrict__ WDB,
    __half* __restrict__ XDA, __half* __restrict__ XDB, int nd,
    int gblocks)
{
    constexpr int RPW = 2;
    constexpr int OPL = DOUT / 32;
    __shared__ float WtA[64][DOUT];
    __shared__ float WtB[64][DOUT];
    __shared__ float hs[8][RPW][64];
    const float *H, *scA, *WA, *scB, *WB; __half *XA, *XB; int n, bid;
    if (blockIdx.x < gblocks) {
        H = Hg; scA = sGA; WA = WGA; scB = sGB; WB = WGB; XA = XGA; XB = XGB;
        n = ng; bid = blockIdx.x;
    } else {
        H = Hd; scA = sDA; WA = WDA; scB = sDB; WB = WDB; XA = XDA; XB = XDB;
        n = nd; bid = blockIdx.x - gblocks;
    }
    const int warp = threadIdx.x >> 5, lane = threadIdx.x & 31;
    const int base = bid * 8 * RPW;
    for (int i = threadIdx.x; i < 64 * DOUT; i += 256) {
        int k = i / DOUT, o = i - k * DOUT;
        WtA[k][o] = WA[(size_t)o * 64 + k];
        WtB[k][o] = WB[(size_t)o * 64 + k];
    }
    #pragma unroll
    for (int rr = 0; rr < RPW; rr++) {
        int r = base + warp * RPW + rr;
        if (r < n) {
            hs[warp][rr][lane]      = H[(size_t)r * 64 + lane];
            hs[warp][rr][lane + 32] = H[(size_t)r * 64 + lane + 32];
        }
    }
    __syncthreads();
    float aA[RPW][OPL], aB[RPW][OPL];
    #pragma unroll
    for (int i = 0; i < RPW; i++)
        #pragma unroll
        for (int o = 0; o < OPL; o++) { aA[i][o] = 0.f; aB[i][o] = 0.f; }
    #pragma unroll
    for (int k = 0; k < 64; k++) {
        float wa0 = WtA[k][lane], wb0 = WtB[k][lane];
        float wa1 = (OPL > 1) ? WtA[k][(OPL > 1 ? lane + 32 : 0)] : 0.f;
        float wb1 = (OPL > 1) ? WtB[k][(OPL > 1 ? lane + 32 : 0)] : 0.f;
        #pragma unroll
        for (int rr = 0; rr < RPW; rr++) {
            float h = hs[warp][rr][k];
            aA[rr][0] = fmaf(h, wa0, aA[rr][0]);
            aB[rr][0] = fmaf(h, wb0, aB[rr][0]);
            if (OPL > 1) {
                aA[rr][1] = fmaf(h, wa1, aA[rr][1]);
                aB[rr][1] = fmaf(h, wb1, aB[rr][1]);
            }
        }
    }
    #pragma unroll
    for (int rr = 0; rr < RPW; rr++) {
        int r = base + warp * RPW + rr;
        if (r < n) {
            float sA = scA[r], sB = scB[r];
            XA[(size_t)r * DOUT + lane] = __float2half_rn(aA[rr][0] * sA);
            XB[(size_t)r * DOUT + lane] = __float2half_rn(aB[rr][0] * sB);
            if (OPL > 1) {
                XA[(size_t)r * DOUT + lane + 32] = __float2half_rn(aA[rr][1] * sA);
                XB[(size_t)r * DOUT + lane + 32] = __float2half_rn(aB[rr][1] * sB);
            }
        }
    }
}

// ------- vectorized CSR gather-sum for one relation: LDG.64, multiple edges/warp -------
// returns per-lane float4 of dims [4d..4d+3] where d = lane % (DOUT/4); reduced across subs
template <int DOUT>
__device__ __forceinline__ float4 agg_one(const int* __restrict__ rp, const int* __restrict__ col,
                                          const __half* __restrict__ x, int v, int lane)
{
    constexpr int LPE = DOUT / 4;   // lanes per edge (16 for D64, 8 for D32)
    constexpr int EPW = 32 / LPE;   // edges per warp step (2 or 4)
    const int sub = lane / LPE;
    const int d = lane - sub * LPE;
    const __half* base = x + d * 4;
    float4 acc = make_float4(0.f, 0.f, 0.f, 0.f);
    int s = rp[v], e = rp[v + 1], j = s;
    for (; j + 2 * EPW <= e; j += 2 * EPW) {
        int u0 = col[j + sub];
        int u1 = col[j + EPW + sub];
        uint2 r0 = *(const uint2*)(base + (size_t)u0 * DOUT);
        uint2 r1 = *(const uint2*)(base + (size_t)u1 * DOUT);
        float2 a0 = __half22float2(*reinterpret_cast<__half2*>(&r0.x));
        float2 a1 = __half22float2(*reinterpret_cast<__half2*>(&r0.y));
        float2 b0 = __half22float2(*reinterpret_cast<__half2*>(&r1.x));
        float2 b1 = __half22float2(*reinterpret_cast<__half2*>(&r1.y));
        acc.x += a0.x + b0.x; acc.y += a0.y + b0.y;
        acc.z += a1.x + b1.x; acc.w += a1.y + b1.y;
    }
    for (; j + EPW <= e; j += EPW) {
        int u = col[j + sub];
        uint2 r0 = *(const uint2*)(base + (size_t)u * DOUT);
        float2 a0 = __half22float2(*reinterpret_cast<__half2*>(&r0.x));
        float2 a1 = __half22float2(*reinterpret_cast<__half2*>(&r0.y));
        acc.x += a0.x; acc.y += a0.y; acc.z += a1.x; acc.w += a1.y;
    }
    if (j + sub < e) {
        int u = col[j + sub];
        uint2 r0 = *(const uint2*)(base + (size_t)u * DOUT);
        float2 a0 = __half22float2(*reinterpret_cast<__half2*>(&r0.x));
        float2 a1 = __half22float2(*reinterpret_cast<__half2*>(&r0.y));
        acc.x += a0.x; acc.y += a0.y; acc.z += a1.x; acc.w += a1.y;
    }
    #pragma unroll
    for (int off = LPE; off < 32; off <<= 1) {
        acc.x += __shfl_xor_sync(0xFFFFFFFFu, acc.x, off);
        acc.y += __shfl_xor_sync(0xFFFFFFFFu, acc.y, off);
        acc.z += __shfl_xor_sync(0xFFFFFFFFu, acc.z, off);
        acc.w += __shfl_xor_sync(0xFFFFFFFFu, acc.w, off);
    }
    return acc;
}

// ------- merged dual-relation aggregation for BOTH node types in one launch -------
// gene part: rows [0,ng) via blocks [0,gblocks); disease part: rows [0,nd) after.
// SPLITG: gene output as fp16 (hi, lo) pair; else fp32. Disease output always fp32.
template <int DOUT, bool SPLITG>
__global__ __launch_bounds__(256) void k_agg_pair(
    const int* __restrict__ rpGA, const int* __restrict__ colGA,
    const __half* __restrict__ xGA, const float* __restrict__ ndGA,
    const int* __restrict__ rpGB, const int* __restrict__ colGB,
    const __half* __restrict__ xGB, const float* __restrict__ ndGB,
    const float* __restrict__ bGA, const float* __restrict__ bGB,
    float* __restrict__ outGf, __half* __restrict__ outGh, __half* __restrict__ outGl, int ng,
    const int* __restrict__ rpDA, const int* __restrict__ colDA,
    const __half* __restrict__ xDA, const float* __restrict__ ndDA,
    const int* __restrict__ rpDB, const int* __restrict__ colDB,
    const __half* __restrict__ xDB, const float* __restrict__ ndDB,
    const float* __restrict__ bDA, const float* __restrict__ bDB,
    float* __restrict__ outDf, int nd, int gblocks)
{
    constexpr int LPE = DOUT / 4;
    const int warp = threadIdx.x >> 5, lane = threadIdx.x & 31;
    const bool gene = (int)blockIdx.x < gblocks;
    const int bid = gene ? blockIdx.x : blockIdx.x - gblocks;
    const int v = bid * 8 + warp;
    if (gene) {
        if (v >= ng) return;
        float4 aA = agg_one<DOUT>(rpGA, colGA, xGA, v, lane);
        float4 aB = agg_one<DOUT>(rpGB, colGB, xGB, v, lane);
        if (lane < LPE) {
            float nA = ndGA[v], nB = ndGB[v];
            float4 bAv = *(const float4*)(bGA + 4 * lane);
            float4 bBv = *(const float4*)(bGB + 4 * lane);
            float4 o;
            o.x = fmaxf(nA * aA.x + nB * aB.x + bAv.x + bBv.x, 0.f);
            o.y = fmaxf(nA * aA.y + nB * aB.y + bAv.y + bBv.y, 0.f);
            o.z = fmaxf(nA * aA.z + nB * aB.z + bAv.z + bBv.z, 0.f);
            o.w = fmaxf(nA * aA.w + nB * aB.w + bAv.w + bBv.w, 0.f);
            if (SPLITG) {
                __half h0 = __float2half_rn(o.x), h1 = __float2half_rn(o.y);
                __half h2 = __float2half_rn(o.z), h3 = __float2half_rn(o.w);
                __half l0 = __float2half_rn(o.x - __half2float(h0));
                __half l1 = __float2half_rn(o.y - __half2float(h1));
                __half l2 = __float2half_rn(o.z - __half2float(h2));
                __half l3 = __float2half_rn(o.w - __half2float(h3));
                __half2 ph0 = __halves2half2(h0, h1), ph1 = __halves2half2(h2, h3);
                __half2 pl0 = __halves2half2(l0, l1), pl1 = __halves2half2(l2, l3);
                uint2 sh, sl;
                sh.x = *reinterpret_cast<uint32_t*>(&ph0); sh.y = *reinterpret_cast<uint32_t*>(&ph1);
                sl.x = *reinterpret_cast<uint32_t*>(&pl0); sl.y = *reinterpret_cast<uint32_t*>(&pl1);
                *(uint2*)(outGh + (size_t)v * DOUT + 4 * lane) = sh;
                *(uint2*)(outGl + (size_t)v * DOUT + 4 * lane) = sl;
            } else {
                *(float4*)(outGf + (size_t)v * DOUT + 4 * lane) = o;
            }
        }
    } else {
        if (v >= nd) return;
        float4 aA = agg_one<DOUT>(rpDA, colDA, xDA, v, lane);
        float4 aB = agg_one<DOUT>(rpDB, colDB, xDB, v, lane);
        if (lane < LPE) {
            float nA = ndDA[v], nB = ndDB[v];
            float4 bAv = *(const float4*)(bDA + 4 * lane);
            float4 bBv = *(const float4*)(bDB + 4 * lane);
            float4 o;
            o.x = fmaxf(nA * aA.x + nB * aB.x + bAv.x + bBv.x, 0.f);
            o.y = fmaxf(nA * aA.y + nB * aB.y + bAv.y + bBv.y, 0.f);
            o.z = fmaxf(nA * aA.z + nB * aB.z + bAv.z + bBv.z, 0.f);
            o.w = fmaxf(nA * aA.w + nB * aB.w + bAv.w + bBv.w, 0.f);
            *(float4*)(outDf + (size_t)v * DOUT + 4 * lane) = o;
        }
    }
}

// ---------------- B side of final GEMM: Y = Hd2 @ Wout, split fp16 (hi, lo) ----------------
__global__ __launch_bounds__(256) void k_wout(
    const float* __restrict__ H, const float* __restrict__ Wout,
    __half* __restrict__ Bh, __half* __restrict__ Bl, int n)
{
    constexpr int RPW = 2;
    __shared__ float Wt[32][32];
    __shared__ float hs[8][RPW][32];
    const int warp = threadIdx.x >> 5, lane = threadIdx.x & 31;
    const int base = blockIdx.x * 8 * RPW;
    for (int i = threadIdx.x; i < 32 * 32; i += 256) {
        int k = i >> 5, o = i & 31;
        Wt[k][o] = Wout[(size_t)k * 32 + o];   // Y = H @ Wout
    }
    #pragma unroll
    for (int rr = 0; rr < RPW; rr++) {
        int r = base + warp * RPW + rr;
        if (r < n) hs[warp][rr][lane] = H[(size_t)r * 32 + lane];
    }
    __syncthreads();
    float acc[RPW];
    #pragma unroll
    for (int i = 0; i < RPW; i++) acc[i] = 0.f;
    #pragma unroll
    for (int k = 0; k < 32; k++) {
        float w = Wt[k][lane];
        #pragma unroll
        for (int rr = 0; rr < RPW; rr++)
            acc[rr] = fmaf(hs[warp][rr][k], w, acc[rr]);
    }
    #pragma unroll
    for (int rr = 0; rr < RPW; rr++) {
        int r = base + warp * RPW + rr;
        if (r < n) {
            __half h = __float2half_rn(acc[rr]);
            __half l = __float2half_rn(acc[rr] - __half2float(h));
            Bh[(size_t)r * 32 + lane] = h;
            Bl[(size_t)r * 32 + lane] = l;
        }
    }
}

// -------- split-fp16 tensor-core GEMM: C = (Ah+Al) @ (Bh+Bl)^T, fp32 accumulate --------
// C += Ah*Bh + Al*Bh + Ah*Bl  (Al*Bl term ~2^-22, omitted)
__global__ __launch_bounds__(256) void k_outgemm_mma(
    const __half* __restrict__ Ah, const __half* __restrict__ Al,
    const __half* __restrict__ Bh, const __half* __restrict__ Bl,
    float* __restrict__ C, int M, int N)
{
    __shared__ float cs[128][68];
    const int warp = threadIdx.x >> 5, lane = threadIdx.x & 31;
    const int wm = warp >> 2;
    const int wn = warp & 3;
    const int mb = blockIdx.y * 128;
    const int nb = blockIdx.x * 64;
    const int m0 = mb + wm * 64;
    const int n0 = nb + wn * 16;
    const int g = lane >> 2;
    const int t = lane & 3;

    float acc[4][2][4];
    #pragma unroll
    for (int mt = 0; mt < 4; mt++)
        #pragma unroll
        for (int nt = 0; nt < 2; nt++)
            #pragma unroll
            for (int q = 0; q < 4; q++) acc[mt][nt][q] = 0.f;

    #pragma unroll
    for (int kt = 0; kt < 2; kt++) {
        const int kb = kt * 16;
        uint32_t afh[4][4], afl[4][4];
        #pragma unroll
        for (int mt = 0; mt < 4; mt++) {
            int r0 = m0 + mt * 16 + g;
            int r1 = r0 + 8;
            afh[mt][0] = (r0 < M) ? *(const uint32_t*)(Ah + (size_t)r0 * 32 + kb + 2 * t) : 0u;
            afh[mt][1] = (r1 < M) ? *(const uint32_t*)(Ah + (size_t)r1 * 32 + kb + 2 * t) : 0u;
            afh[mt][2] = (r0 < M) ? *(const uint32_t*)(Ah + (size_t)r0 * 32 + kb + 8 + 2 * t) : 0u;
            afh[mt][3] = (r1 < M) ? *(const uint32_t*)(Ah + (size_t)r1 * 32 + kb + 8 + 2 * t) : 0u;
            afl[mt][0] = (r0 < M) ? *(const uint32_t*)(Al + (size_t)r0 * 32 + kb + 2 * t) : 0u;
            afl[mt][1] = (r1 < M) ? *(const uint32_t*)(Al + (size_t)r1 * 32 + kb + 2 * t) : 0u;
            afl[mt][2] = (r0 < M) ? *(const uint32_t*)(Al + (size_t)r0 * 32 + kb + 8 + 2 * t) : 0u;
            afl[mt][3] = (r1 < M) ? *(const uint32_t*)(Al + (size_t)r1 * 32 + kb + 8 + 2 * t) : 0u;
        }
        #pragma unroll
        for (int nt = 0; nt < 2; nt++) {
            int c = n0 + nt * 8 + g;
            uint32_t bh0 = (c < N) ? *(const uint32_t*)(Bh + (size_t)c * 32 + kb + 2 * t) : 0u;
            uint32_t bh1 = (c < N) ? *(const uint32_t*)(Bh + (size_t)c * 32 + kb + 8 + 2 * t) : 0u;
            uint32_t bl0 = (c < N) ? *(const uint32_t*)(Bl + (size_t)c * 32 + kb + 2 * t) : 0u;
            uint32_t bl1 = (c < N) ? *(const uint32_t*)(Bl + (size_t)c * 32 + kb + 8 + 2 * t) : 0u;
            #pragma unroll
            for (int mt = 0; mt < 4; mt++) {
                asm volatile(
                    "mma.sync.aligned.m16n8k16.row.col.f32.f16.f16.f32 "
                    "{%0,%1,%2,%3}, {%4,%5,%6,%7}, {%8,%9}, {%0,%1,%2,%3};"
                    : "+f"(acc[mt][nt][0]), "+f"(acc[mt][nt][1]),
                      "+f"(acc[mt][nt][2]), "+f"(acc[mt][nt][3])
                    : "r"(afh[mt][0]), "r"(afh[mt][1]), "r"(afh[mt][2]), "r"(afh[mt][3]),
                      "r"(bh0), "r"(bh1));
                asm volatile(
                    "mma.sync.aligned.m16n8k16.row.col.f32.f16.f16.f32 "
                    "{%0,%1,%2,%3}, {%4,%5,%6,%7}, {%8,%9}, {%0,%1,%2,%3};"
                    : "+f"(acc[mt][nt][0]), "+f"(acc[mt][nt][1]),
                      "+f"(acc[mt][nt][2]), "+f"(acc[mt][nt][3])
                    : "r"(afl[mt][0]), "r"(afl[mt][1]), "r"(afl[mt][2]), "r"(afl[mt][3]),
                      "r"(bh0), "r"(bh1));
                asm volatile(
                    "mma.sync.aligned.m16n8k16.row.col.f32.f16.f16.f32 "
                    "{%0,%1,%2,%3}, {%4,%5,%6,%7}, {%8,%9}, {%0,%1,%2,%3};"
                    : "+f"(acc[mt][nt][0]), "+f"(acc[mt][nt][1]),
                      "+f"(acc[mt][nt][2]), "+f"(acc[mt][nt][3])
                    : "r"(afh[mt][0]), "r"(afh[mt][1]), "r"(afh[mt][2]), "r"(afh[mt][3]),
                      "r"(bl0), "r"(bl1));
            }
        }
    }

    #pragma unroll
    for (int mt = 0; mt < 4; mt++) {
        int rr = wm * 64 + mt * 16 + g;
        #pragma unroll
        for (int nt = 0; nt < 2; nt++) {
            int cc = wn * 16 + nt * 8 + 2 * t;
            cs[rr][cc]         = acc[mt][nt][0];
            cs[rr][cc + 1]     = acc[mt][nt][1];
            cs[rr + 8][cc]     = acc[mt][nt][2];
            cs[rr + 8][cc + 1] = acc[mt][nt][3];
        }
    }
    __syncthreads();
    for (int i = threadIdx.x; i < 128 * 16; i += 256) {
        int row = i >> 4, c4 = (i & 15) << 2;
        int m = mb + row, n = nb + c4;
        if (m >= M) continue;
        if (n + 3 < N) {
            *(float4*)(C + (size_t)m * N + n) =
                make_float4(cs[row][c4], cs[row][c4 + 1], cs[row][c4 + 2], cs[row][c4 + 3]);
        } else {
            for (int q = 0; q < 4; q++)
                if (n + q < N) C[(size_t)m * N + n + q] = cs[row][c4 + q];
        }
    }
}

// ---------------- launch ----------------
#define SYMP(var, T, sym) do { void* _p; cudaGetSymbolAddress(&_p, sym); var = (T*)_p; } while (0)

extern "C" void kernel_launch(void* const* d_in, const int* in_sizes, int n_in,
                              void* d_out, int out_size)
{
    const float* feat_g = (const float*)d_in[0];
    const float* feat_d = (const float*)d_in[1];
    const int* gg_src = (const int*)d_in[2];
    const int* gg_dst = (const int*)d_in[3];
    const int* gd_src = (const int*)d_in[4];
    const int* gd_dst = (const int*)d_in[5];
    const int* dd_src = (const int*)d_in[6];
    const int* dd_dst = (const int*)d_in[7];
    const float* Wg   = (const float*)d_in[8];
    const float* Wd   = (const float*)d_in[9];
    const float* W1   = (const float*)d_in[10];
    const float* b1   = (const float*)d_in[11];
    const float* W2   = (const float*)d_in[12];
    const float* b2   = (const float*)d_in[13];
    const float* Wout = (const float*)d_in[14];
    const int n_gg = in_sizes[2], n_gd = in_sizes[4], n_dd = in_sizes[6];

    int *rp_gg, *rp_dg, *rp_gd, *rp_dd;
    int *col_gg, *col_dg, *col_gd, *col_dd;
    float *rs_gg_src, *rs_gg_dst, *rs_gd_src, *rs_gd_dst, *rs_dd_src, *rs_dd_dst;
    float *hg, *hd, *og, *od;
    __half *xga, *xgb, *xda, *xdb, *ah, *al, *bh, *bl;
    SYMP(rp_gg, int, g_rp_gg); SYMP(rp_dg, int, g_rp_dg);
    SYMP(rp_gd, int, g_rp_gd); SYMP(rp_dd, int, g_rp_dd);
    SYMP(col_gg, int, g_col_gg); SYMP(col_dg, int, g_col_dg);
    SYMP(col_gd, int, g_col_gd); SYMP(col_dd, int, g_col_dd);
    SYMP(rs_gg_src, float, g_rs_gg_src); SYMP(rs_gg_dst, float, g_rs_gg_dst);
    SYMP(rs_gd_src, float, g_rs_gd_src); SYMP(rs_gd_dst, float, g_rs_gd_dst);
    SYMP(rs_dd_src, float, g_rs_dd_src); SYMP(rs_dd_dst, float, g_rs_dd_dst);
    SYMP(hg, float, g_hg); SYMP(hd, float, g_hd);
    SYMP(og, float, g_og); SYMP(od, float, g_od);
    SYMP(xga, __half, g_xga); SYMP(xgb, __half, g_xgb);
    SYMP(xda, __half, g_xda); SYMP(xdb, __half, g_xdb);
    SYMP(ah, __half, g_ah);
    al = (__half*)og;   // og free during layer-2 agg (consumed by layer-2 transforms)
    bh = xda;           // xda/xdb free after layer-2 agg
    bl = xdb;

    // 1) degrees + CSR build
    k_zero_counts<<<(NGN + 255) / 256, 256>>>();
    k_hist_all<<<1480, 256>>>(gg_src, gg_dst, gd_src, gd_dst, dd_src, dd_dst,
                              n_gg, n_gd, n_dd);
    k_setup2<<<4 + (NGN + 1023) / 1024, 1024>>>();
    k_scatter_all<<<1480, 256>>>(gg_src, gg_dst, gd_src, gd_dst, dd_src, dd_dst,
                                 n_gg, n_gd, n_dd);

    // 2) embeddings (both node types, one launch)
    {
        int gb = (NGN + 31) / 32, db = (NDN + 31) / 32;
        k_embed_pair<<<gb + db, 256>>>(feat_g, Wg, hg, NGN, feat_d, Wd, hd, NDN, gb);
    }

    // 3) layer 1 (H1=64)
    {
        int gb = (NGN + 15) / 16, db = (NDN + 15) / 16;
        k_t2_pair<64><<<gb + db, 256>>>(
            hg, rs_gg_src, W1 + 0 * 64 * 64, rs_gd_src, W1 + 1 * 64 * 64, xga, xgb, NGN,
            hd, rs_gd_dst, W1 + 2 * 64 * 64, rs_dd_src, W1 + 3 * 64 * 64, xda, xdb, NDN, gb);
    }
    {
        int gb = (NGN + 7) / 8, db = (NDN + 7) / 8;
        k_agg_pair<64, false><<<gb + db, 256>>>(
            rp_gg, col_gg, xga, rs_gg_dst, rp_dg, col_dg, xda, rs_gd_src,
            b1 + 0 * 64, b1 + 2 * 64, og, nullptr, nullptr, NGN,
            rp_gd, col_gd, xgb, rs_gd_dst, rp_dd, col_dd, xdb, rs_dd_dst,
            b1 + 1 * 64, b1 + 3 * 64, od, NDN, gb);
    }

    // 4) layer 2 (H2=32)
    {
        int gb = (NGN + 15) / 16, db = (NDN + 15) / 16;
        k_t2_pair<32><<<gb + db, 256>>>(
            og, rs_gg_src, W2 + 0 * 32 * 64, rs_gd_src, W2 + 1 * 32 * 64, xga, xgb, NGN,
            od, rs_gd_dst, W2 + 2 * 32 * 64, rs_dd_src, W2 + 3 * 32 * 64, xda, xdb, NDN, gb);
    }
    {
        int gb = (NGN + 7) / 8, db = (NDN + 7) / 8;
        k_agg_pair<32, true><<<gb + db, 256>>>(
            rp_gg, col_gg, xga, rs_gg_dst, rp_dg, col_dg, xda, rs_gd_src,
            b2 + 0 * 32, b2 + 2 * 32, nullptr, ah, al, NGN,          // gene: fp16 hi/lo
            rp_gd, col_gd, xgb, rs_gd_dst, rp_dd, col_dd, xdb, rs_dd_dst,
            b2 + 1 * 32, b2 + 3 * 32, hd, NDN, gb);                  // disease: fp32
    }

    // 5) B = hd2 @ Wout (split fp16) ; out = A @ B^T via split-fp16 tensor cores
    k_wout<<<(NDN + 15) / 16, 256>>>(hd, Wout, bh, bl, NDN);
    dim3 grid((NDN + 63) / 64, (NGN + 127) / 128);
    k_outgemm_mma<<<grid, 256>>>(ah, al, bh, bl, (float*)d_out, NGN, NDN);
}